// round 2
// baseline (speedup 1.0000x reference)
#include <cuda_runtime.h>
#include <math.h>

#define NHEAD 16
#define DH    64
#define DM    1024
#define BATCH 2
#define LEN   2048

// Scratch for projected q,k,v in [B, H, L, DH] layout (16.8 MB each).
__device__ float g_q[(size_t)BATCH * NHEAD * LEN * DH];
__device__ float g_k[(size_t)BATCH * NHEAD * LEN * DH];
__device__ float g_v[(size_t)BATCH * NHEAD * LEN * DH];

// ---------------------------------------------------------------------------
// Projection GEMM: C[r, c] = sum_k X[r, k] * W[k, c]
// X: [B*L, DM] row-major, W: [DM, DM] row-major.
// Output written directly into [B, H, L, DH] layout.
// Tile: 64x64x16, 256 threads, 4x4 micro-tile per thread.
// blockIdx.z selects (Q,WQ)->g_q, (K,WK)->g_k, (V,WV)->g_v.
// Note: N-tile of 64 == exactly one head (DH=64), so head = blockIdx.x.
// ---------------------------------------------------------------------------
__global__ __launch_bounds__(256) void proj_kernel(
    const float* __restrict__ Q, const float* __restrict__ K,
    const float* __restrict__ V,
    const float* __restrict__ WQ, const float* __restrict__ WK,
    const float* __restrict__ WV)
{
    const float* X;
    const float* W;
    float* O;
    int z = blockIdx.z;
    if (z == 0)      { X = Q; W = WQ; O = g_q; }
    else if (z == 1) { X = K; W = WK; O = g_k; }
    else             { X = V; W = WV; O = g_v; }

    __shared__ float As[16][64];   // [k][m] (transposed for contiguous micro-tile reads)
    __shared__ float Bs[16][64];   // [k][n]

    const int tid = threadIdx.x;
    const int tx = tid & 15;
    const int ty = tid >> 4;
    const int m0 = blockIdx.y * 64;
    const int n0 = blockIdx.x * 64;

    // load indexing
    const int arow = tid >> 2;          // 0..63
    const int ak   = (tid & 3) * 4;     // 0,4,8,12
    const int bk   = tid >> 4;          // 0..15
    const int bn   = (tid & 15) * 4;    // 0..60

    float acc[4][4] = {};

    for (int k0 = 0; k0 < DM; k0 += 16) {
        float4 a = *(const float4*)&X[(size_t)(m0 + arow) * DM + k0 + ak];
        As[ak + 0][arow] = a.x;
        As[ak + 1][arow] = a.y;
        As[ak + 2][arow] = a.z;
        As[ak + 3][arow] = a.w;
        float4 b = *(const float4*)&W[(size_t)(k0 + bk) * DM + n0 + bn];
        *(float4*)&Bs[bk][bn] = b;
        __syncthreads();

        #pragma unroll
        for (int kk = 0; kk < 16; ++kk) {
            float4 av = *(const float4*)&As[kk][ty * 4];
            float4 bv = *(const float4*)&Bs[kk][tx * 4];
            float a4[4] = {av.x, av.y, av.z, av.w};
            float b4[4] = {bv.x, bv.y, bv.z, bv.w};
            #pragma unroll
            for (int i = 0; i < 4; ++i)
                #pragma unroll
                for (int j = 0; j < 4; ++j)
                    acc[i][j] = fmaf(a4[i], b4[j], acc[i][j]);
        }
        __syncthreads();
    }

    // writeback: row r = b*LEN + l, col-tile = one head
    const int head = blockIdx.x;
    #pragma unroll
    for (int i = 0; i < 4; ++i) {
        int r = m0 + ty * 4 + i;
        int bb = r >> 11;        // / LEN
        int l  = r & (LEN - 1);
        float4 o4 = make_float4(acc[i][0], acc[i][1], acc[i][2], acc[i][3]);
        *(float4*)&O[(((size_t)bb * NHEAD + head) * LEN + l) * DH + tx * 4] = o4;
    }
}

// ---------------------------------------------------------------------------
// Flash-style attention. One block = (b, h, 64 q-rows), 64 threads,
// one q-row per thread. K/V tiles of 64 keys in shared memory.
// Key mask: loop only over keys < v_len (identical to reference's -1e12
// additive mask: exp underflows to exactly 0 in fp32).
// Query mask: rows >= q_len written as zeros.
// ---------------------------------------------------------------------------
__global__ __launch_bounds__(64) void attn_kernel(
    const int* __restrict__ qlen_p, const int* __restrict__ vlen_p,
    float* __restrict__ Out)
{
    extern __shared__ char smem_raw[];
    float4* k_sm = (float4*)smem_raw;            // [64][16] float4  (16 KB)
    float4* v_sm = k_sm + 64 * 16;               // [64][16] float4  (16 KB)
    float*  s_sm = (float*)(v_sm + 64 * 16);     // [key][tid] 64x64 (16 KB)

    const int b = blockIdx.z;
    const int h = blockIdx.y;
    const int tid = threadIdx.x;
    const int l = blockIdx.x * 64 + tid;
    const int qlen = qlen_p[b];
    const int vlen = vlen_p[b];

    const float* qptr  = &g_q[(((size_t)b * NHEAD + h) * LEN + l) * DH];
    const float* kbase = &g_k[((size_t)b * NHEAD + h) * LEN * DH];
    const float* vbase = &g_v[((size_t)b * NHEAD + h) * LEN * DH];

    const bool active = (l < qlen);

    float4 q[16];
    if (active) {
        #pragma unroll
        for (int i = 0; i < 16; ++i) {
            float4 t = *(const float4*)&qptr[i * 4];
            // fold in 1/sqrt(DH) = 0.125 exactly
            t.x *= 0.125f; t.y *= 0.125f; t.z *= 0.125f; t.w *= 0.125f;
            q[i] = t;
        }
    }

    float4 o[16];
    #pragma unroll
    for (int i = 0; i < 16; ++i) o[i] = make_float4(0.f, 0.f, 0.f, 0.f);

    float mrow = -INFINITY;
    float lsum = 0.f;

    const int ntile = (vlen + 63) >> 6;
    for (int t = 0; t < ntile; ++t) {
        const int k0 = t * 64;
        const int nk = min(64, vlen - k0);

        __syncthreads();   // previous iteration's smem reads done
        const float4* kg = (const float4*)&kbase[(size_t)k0 * DH];
        const float4* vg = (const float4*)&vbase[(size_t)k0 * DH];
        #pragma unroll
        for (int i = 0; i < 16; ++i) {
            int idx = tid + i * 64;
            k_sm[idx] = kg[idx];
            v_sm[idx] = vg[idx];
        }
        __syncthreads();

        if (active) {
            // pass 1: scores + tile max
            float tmax = -INFINITY;
            for (int key = 0; key < nk; ++key) {
                const float4* kr = &k_sm[key * 16];
                float s = 0.f;
                #pragma unroll
                for (int i = 0; i < 16; ++i) {
                    float4 kv = kr[i];
                    s = fmaf(q[i].x, kv.x, s);
                    s = fmaf(q[i].y, kv.y, s);
                    s = fmaf(q[i].z, kv.z, s);
                    s = fmaf(q[i].w, kv.w, s);
                }
                s_sm[key * 64 + tid] = s;
                tmax = fmaxf(tmax, s);
            }
            // online softmax rescale (once per tile)
            float mnew = fmaxf(mrow, tmax);
            float corr = __expf(mrow - mnew);   // exp(-inf)=0 on first tile
            lsum *= corr;
            #pragma unroll
            for (int i = 0; i < 16; ++i) {
                o[i].x *= corr; o[i].y *= corr; o[i].z *= corr; o[i].w *= corr;
            }
            // pass 2: exp + accumulate O
            for (int key = 0; key < nk; ++key) {
                float p = __expf(s_sm[key * 64 + tid] - mnew);
                lsum += p;
                const float4* vr = &v_sm[key * 16];
                #pragma unroll
                for (int i = 0; i < 16; ++i) {
                    float4 vv = vr[i];
                    o[i].x = fmaf(p, vv.x, o[i].x);
                    o[i].y = fmaf(p, vv.y, o[i].y);
                    o[i].z = fmaf(p, vv.z, o[i].z);
                    o[i].w = fmaf(p, vv.w, o[i].w);
                }
            }
            mrow = mnew;
        }
    }

    float* outp = &Out[((size_t)b * LEN + l) * DM + h * DH];
    if (active) {
        float inv = 1.0f / lsum;
        #pragma unroll
        for (int i = 0; i < 16; ++i) {
            float4 r = o[i];
            r.x *= inv; r.y *= inv; r.z *= inv; r.w *= inv;
            *(float4*)&outp[i * 4] = r;
        }
    } else {
        float4 zero = make_float4(0.f, 0.f, 0.f, 0.f);
        #pragma unroll
        for (int i = 0; i < 16; ++i)
            *(float4*)&outp[i * 4] = zero;
    }
}

// ---------------------------------------------------------------------------
extern "C" void kernel_launch(void* const* d_in, const int* in_sizes, int n_in,
                              void* d_out, int out_size)
{
    const float* Q_seq = (const float*)d_in[0];
    const float* K_seq = (const float*)d_in[1];
    const float* V_seq = (const float*)d_in[2];
    const int*   q_len = (const int*)d_in[3];
    const int*   v_len = (const int*)d_in[4];
    const float* WQ    = (const float*)d_in[5];
    const float* WK    = (const float*)d_in[6];
    const float* WV    = (const float*)d_in[7];
    float* Out = (float*)d_out;

    // QKV projections
    dim3 pgrid(DM / 64, (BATCH * LEN) / 64, 3);
    proj_kernel<<<pgrid, 256>>>(Q_seq, K_seq, V_seq, WQ, WK, WV);

    // Attention
    const int smem = 64 * 16 * 16 * 2 + 64 * 64 * 4;  // 49152 bytes
    static bool attr_set = false;
    if (!attr_set) {
        cudaFuncSetAttribute(attn_kernel,
                             cudaFuncAttributeMaxDynamicSharedMemorySize, smem);
        attr_set = true;
    }
    dim3 agrid(LEN / 64, NHEAD, BATCH);
    attn_kernel<<<agrid, 64, smem>>>(q_len, v_len, Out);
}

// round 3
// speedup vs baseline: 1.0256x; 1.0256x over previous
#include <cuda_runtime.h>
#include <math.h>

#define NHEAD 16
#define DH    64
#define DM    1024
#define BATCH 2
#define LEN   2048

#define ATTN_ROWS 128
#define KTILE 64

// Scratch for projected q,k,v in [B, H, L, DH] layout (16.8 MB each).
__device__ float g_q[(size_t)BATCH * NHEAD * LEN * DH];
__device__ float g_k[(size_t)BATCH * NHEAD * LEN * DH];
__device__ float g_v[(size_t)BATCH * NHEAD * LEN * DH];

// ---------------------------------------------------------------------------
// Projection GEMM: C[r, c] = sum_k X[r, k] * W[k, c]
// X: [B*L, DM] row-major, W: [DM, DM] row-major.
// Output written directly into [B, H, L, DH] layout.
// Tile: 128x128x16, 256 threads, 8x8 micro-tile, register prefetch.
// blockIdx.z selects (Q,WQ)->g_q, (K,WK)->g_k, (V,WV)->g_v.
// ---------------------------------------------------------------------------
__global__ __launch_bounds__(256) void proj_kernel(
    const float* __restrict__ Q, const float* __restrict__ K,
    const float* __restrict__ V,
    const float* __restrict__ WQ, const float* __restrict__ WK,
    const float* __restrict__ WV)
{
    const float* X;
    const float* W;
    float* O;
    int z = blockIdx.z;
    if (z == 0)      { X = Q; W = WQ; O = g_q; }
    else if (z == 1) { X = K; W = WK; O = g_k; }
    else             { X = V; W = WV; O = g_v; }

    __shared__ float As[16][128];   // [k][m] (m contiguous)
    __shared__ float Bs[16][128];   // [k][n]

    const int tid = threadIdx.x;
    const int tx = tid & 15;        // 16 col positions
    const int ty = tid >> 4;        // 16 row positions
    const int m0 = blockIdx.y * 128;
    const int n0 = blockIdx.x * 128;

    // A load: thread -> row m0+am, k-offsets {ak..ak+3, ak+8..ak+11}
    const int am = tid & 127;
    const int ak = (tid >> 7) << 2;         // 0 or 4
    // B load: thread -> k rows {bk, bk+8}, n-offset bn..bn+3
    const int bn = (tid & 31) << 2;
    const int bk = tid >> 5;                // 0..7

    const float* Aptr = X + (size_t)(m0 + am) * DM;
    const float* Bptr = W + n0 + bn;

    float4 pa0 = *(const float4*)(Aptr + ak);
    float4 pa1 = *(const float4*)(Aptr + ak + 8);
    float4 pb0 = *(const float4*)(Bptr + (size_t)bk * DM);
    float4 pb1 = *(const float4*)(Bptr + (size_t)(bk + 8) * DM);

    float acc[8][8] = {};

    for (int k0 = 0; k0 < DM; k0 += 16) {
        As[ak + 0][am] = pa0.x;  As[ak + 1][am] = pa0.y;
        As[ak + 2][am] = pa0.z;  As[ak + 3][am] = pa0.w;
        As[ak + 8][am] = pa1.x;  As[ak + 9][am] = pa1.y;
        As[ak + 10][am] = pa1.z; As[ak + 11][am] = pa1.w;
        *(float4*)&Bs[bk][bn] = pb0;
        *(float4*)&Bs[bk + 8][bn] = pb1;
        __syncthreads();

        if (k0 + 16 < DM) {
            pa0 = *(const float4*)(Aptr + k0 + 16 + ak);
            pa1 = *(const float4*)(Aptr + k0 + 16 + ak + 8);
            pb0 = *(const float4*)(Bptr + (size_t)(k0 + 16 + bk) * DM);
            pb1 = *(const float4*)(Bptr + (size_t)(k0 + 16 + bk + 8) * DM);
        }

        #pragma unroll
        for (int kk = 0; kk < 16; ++kk) {
            float4 a0 = *(const float4*)&As[kk][ty * 8];
            float4 a1 = *(const float4*)&As[kk][ty * 8 + 4];
            float4 b0 = *(const float4*)&Bs[kk][tx * 8];
            float4 b1 = *(const float4*)&Bs[kk][tx * 8 + 4];
            float a[8] = {a0.x, a0.y, a0.z, a0.w, a1.x, a1.y, a1.z, a1.w};
            float bb[8] = {b0.x, b0.y, b0.z, b0.w, b1.x, b1.y, b1.z, b1.w};
            #pragma unroll
            for (int i = 0; i < 8; ++i)
                #pragma unroll
                for (int j = 0; j < 8; ++j)
                    acc[i][j] = fmaf(a[i], bb[j], acc[i][j]);
        }
        __syncthreads();
    }

    // writeback into [B, H, L, DH]
    const int head = (n0 >> 6) + (tx >> 3);
    const int col_in = (tx & 7) * 8;
    #pragma unroll
    for (int i = 0; i < 8; ++i) {
        int r = m0 + ty * 8 + i;
        int bb_ = r >> 11;          // / LEN
        int l   = r & (LEN - 1);
        float* dst = &O[(((size_t)bb_ * NHEAD + head) * LEN + l) * DH + col_in];
        *(float4*)dst       = make_float4(acc[i][0], acc[i][1], acc[i][2], acc[i][3]);
        *(float4*)(dst + 4) = make_float4(acc[i][4], acc[i][5], acc[i][6], acc[i][7]);
    }
}

// ---------------------------------------------------------------------------
// Flash-style attention, single-pass online softmax (no score smem).
// One block = (b, h, 128 q-rows), 128 threads, one q-row per thread.
// K/V tiles of 64 keys in shared memory (32 KB).
// Key mask: loop only over keys < v_len (exp(-1e12) == 0 in fp32, identical).
// Query mask: rows >= q_len written as zeros; fully-dead blocks exit early.
// ---------------------------------------------------------------------------
__global__ __launch_bounds__(128) void attn_kernel(
    const int* __restrict__ qlen_p, const int* __restrict__ vlen_p,
    float* __restrict__ Out)
{
    __shared__ float4 k_sm[KTILE * 16];   // [key][16 float4]
    __shared__ float4 v_sm[KTILE * 16];

    const int b = blockIdx.z;
    const int h = blockIdx.y;
    const int tid = threadIdx.x;
    const int l = blockIdx.x * ATTN_ROWS + tid;
    const int qlen = qlen_p[b];
    const int vlen = vlen_p[b];

    float* outp = &Out[((size_t)b * LEN + l) * DM + h * DH];

    // whole block dead -> write zeros, skip the K/V loop entirely
    if (blockIdx.x * ATTN_ROWS >= qlen) {
        float4 zero = make_float4(0.f, 0.f, 0.f, 0.f);
        #pragma unroll
        for (int i = 0; i < 16; ++i)
            *(float4*)&outp[i * 4] = zero;
        return;
    }

    const bool active = (l < qlen);

    const float* qptr  = &g_q[(((size_t)b * NHEAD + h) * LEN + l) * DH];
    const float* kbase = &g_k[((size_t)b * NHEAD + h) * LEN * DH];
    const float* vbase = &g_v[((size_t)b * NHEAD + h) * LEN * DH];

    float4 q[16];
    #pragma unroll
    for (int i = 0; i < 16; ++i) {
        if (active) {
            float4 t = *(const float4*)&qptr[i * 4];
            t.x *= 0.125f; t.y *= 0.125f; t.z *= 0.125f; t.w *= 0.125f;  // 1/sqrt(64)
            q[i] = t;
        } else {
            q[i] = make_float4(0.f, 0.f, 0.f, 0.f);
        }
    }

    float4 o[16];
    #pragma unroll
    for (int i = 0; i < 16; ++i) o[i] = make_float4(0.f, 0.f, 0.f, 0.f);

    float m = -INFINITY;
    float lsum = 0.f;

    const int ntile = (vlen + KTILE - 1) / KTILE;
    for (int t = 0; t < ntile; ++t) {
        const int k0 = t * KTILE;
        const int nk = min(KTILE, vlen - k0);

        const float4* kg = (const float4*)&kbase[(size_t)k0 * DH];
        const float4* vg = (const float4*)&vbase[(size_t)k0 * DH];
        #pragma unroll
        for (int i = 0; i < 8; ++i) {
            int idx = tid + i * 128;
            k_sm[idx] = kg[idx];
            v_sm[idx] = vg[idx];
        }
        __syncthreads();

        for (int key = 0; key < nk; ++key) {
            const float4* kr = &k_sm[key * 16];
            float s = 0.f;
            #pragma unroll
            for (int i = 0; i < 16; ++i) {
                float4 kv = kr[i];
                s = fmaf(q[i].x, kv.x, s);
                s = fmaf(q[i].y, kv.y, s);
                s = fmaf(q[i].z, kv.z, s);
                s = fmaf(q[i].w, kv.w, s);
            }
            if (s > m) {   // new running max: rescale (rare, amortized O(log n))
                float corr = __expf(m - s);   // exp(-inf)=0 on first key
                lsum *= corr;
                #pragma unroll
                for (int i = 0; i < 16; ++i) {
                    o[i].x *= corr; o[i].y *= corr;
                    o[i].z *= corr; o[i].w *= corr;
                }
                m = s;
            }
            float p = __expf(s - m);          // == 1 when s is the new max
            lsum += p;
            const float4* vr = &v_sm[key * 16];
            #pragma unroll
            for (int i = 0; i < 16; ++i) {
                float4 vv = vr[i];
                o[i].x = fmaf(p, vv.x, o[i].x);
                o[i].y = fmaf(p, vv.y, o[i].y);
                o[i].z = fmaf(p, vv.z, o[i].z);
                o[i].w = fmaf(p, vv.w, o[i].w);
            }
        }
        __syncthreads();
    }

    if (active) {
        float inv = 1.0f / lsum;
        #pragma unroll
        for (int i = 0; i < 16; ++i) {
            float4 r = o[i];
            r.x *= inv; r.y *= inv; r.z *= inv; r.w *= inv;
            *(float4*)&outp[i * 4] = r;
        }
    } else {
        float4 zero = make_float4(0.f, 0.f, 0.f, 0.f);
        #pragma unroll
        for (int i = 0; i < 16; ++i)
            *(float4*)&outp[i * 4] = zero;
    }
}

// ---------------------------------------------------------------------------
extern "C" void kernel_launch(void* const* d_in, const int* in_sizes, int n_in,
                              void* d_out, int out_size)
{
    const float* Q_seq = (const float*)d_in[0];
    const float* K_seq = (const float*)d_in[1];
    const float* V_seq = (const float*)d_in[2];
    const int*   q_len = (const int*)d_in[3];
    const int*   v_len = (const int*)d_in[4];
    const float* WQ    = (const float*)d_in[5];
    const float* WK    = (const float*)d_in[6];
    const float* WV    = (const float*)d_in[7];
    float* Out = (float*)d_out;

    // QKV projections: 128x128 tiles
    dim3 pgrid(DM / 128, (BATCH * LEN) / 128, 3);
    proj_kernel<<<pgrid, 256>>>(Q_seq, K_seq, V_seq, WQ, WK, WV);

    // Attention
    dim3 agrid(LEN / ATTN_ROWS, NHEAD, BATCH);
    attn_kernel<<<agrid, 128>>>(q_len, v_len, Out);
}

// round 7
// speedup vs baseline: 1.3547x; 1.3209x over previous
#include <cuda_runtime.h>
#include <math.h>
#include <stdint.h>

#define NHEAD 16
#define DH    64
#define DM    1024
#define BATCH 2
#define LEN   2048

#define ATTN_ROWS 128
#define KTILE 64

// Scratch: projected q,k,v in [B, H, L, DH] layout + transposed weights.
__device__ float g_q[(size_t)BATCH * NHEAD * LEN * DH];
__device__ float g_k[(size_t)BATCH * NHEAD * LEN * DH];
__device__ float g_v[(size_t)BATCH * NHEAD * LEN * DH];
__device__ float g_wt[(size_t)3 * DM * DM];   // W^T for Q,K,V: [n][k]

__device__ __forceinline__ uint32_t f32_to_tf32(float x) {
    uint32_t r;
    asm("cvt.rna.tf32.f32 %0, %1;" : "=r"(r) : "f"(x));
    return r;
}

// m16n8k8 tf32 MMA (sm_80 baseline instruction, runs on tensor core)
__device__ __forceinline__ void mma_tf32(float* c, const uint32_t* a,
                                         uint32_t b0, uint32_t b1) {
    asm volatile(
        "mma.sync.aligned.m16n8k8.row.col.f32.tf32.tf32.f32 "
        "{%0,%1,%2,%3}, {%4,%5,%6,%7}, {%8,%9}, {%0,%1,%2,%3};"
        : "+f"(c[0]), "+f"(c[1]), "+f"(c[2]), "+f"(c[3])
        : "r"(a[0]), "r"(a[1]), "r"(a[2]), "r"(a[3]), "r"(b0), "r"(b1));
}

// ---------------------------------------------------------------------------
// Weight transpose: W[k][n] (row-major) -> WT[n][k]; z = 0,1,2 for WQ,WK,WV.
// ---------------------------------------------------------------------------
__global__ __launch_bounds__(256) void wt_kernel(
    const float* __restrict__ WQ, const float* __restrict__ WK,
    const float* __restrict__ WV)
{
    __shared__ float t[32][33];
    const float* W = (blockIdx.z == 0) ? WQ : (blockIdx.z == 1) ? WK : WV;
    float* WT = g_wt + (size_t)blockIdx.z * DM * DM;

    const int n0 = blockIdx.x * 32;
    const int k0 = blockIdx.y * 32;
    const int tx = threadIdx.x;   // 0..31
    const int ty = threadIdx.y;   // 0..7

    #pragma unroll
    for (int j = 0; j < 4; ++j)
        t[ty + j * 8][tx] = W[(size_t)(k0 + ty + j * 8) * DM + n0 + tx];
    __syncthreads();
    #pragma unroll
    for (int j = 0; j < 4; ++j)
        WT[(size_t)(n0 + ty + j * 8) * DM + k0 + tx] = t[tx][ty + j * 8];
}

// ---------------------------------------------------------------------------
// Projection GEMM on mma.sync tf32: C[r,n] = sum_k X[r,k] * WT[n,k].
// Tile 128x128x32, 256 threads (8 warps, 4x2 warp grid, 32x64 per warp).
// Output written directly into [B, H, L, DH] layout.
// ---------------------------------------------------------------------------
#define BK 32
#define KPAD 36   // row stride in words: bank = (4*row_grp + k)&31, conflict-free

__global__ __launch_bounds__(256) void proj_mma_kernel(
    const float* __restrict__ Q, const float* __restrict__ K,
    const float* __restrict__ V)
{
    __shared__ uint32_t As[128][KPAD];   // [m][k] tf32 bits
    __shared__ uint32_t Bs[128][KPAD];   // [n][k] tf32 bits

    const int z = blockIdx.z;
    const float* X  = (z == 0) ? Q : (z == 1) ? K : V;
    const float* WT = g_wt + (size_t)z * DM * DM;
    float* O        = (z == 0) ? g_q : (z == 1) ? g_k : g_v;

    const int tid  = threadIdx.x;
    const int wid  = tid >> 5;
    const int lane = tid & 31;
    const int wm   = wid & 3;    // 4 warps along m: 32 rows each
    const int wn   = wid >> 2;   // 2 warps along n: 64 cols each
    const int m0   = blockIdx.y * 128;
    const int n0   = blockIdx.x * 128;

    const int g = lane >> 2;     // group id 0..7
    const int t = lane & 3;      // thread-in-group 0..3

    float acc[2][8][4];
    #pragma unroll
    for (int i = 0; i < 2; ++i)
        #pragma unroll
        for (int j = 0; j < 8; ++j)
            #pragma unroll
            for (int c = 0; c < 4; ++c) acc[i][j][c] = 0.f;

    // gmem load coords: row = (tid>>3) + r*32, 16B col group = tid&7
    const int lrow = tid >> 3;
    const int lc4  = (tid & 7) * 4;

    for (int k0 = 0; k0 < DM; k0 += BK) {
        #pragma unroll
        for (int r = 0; r < 4; ++r) {
            const int row = lrow + r * 32;
            float4 a = *(const float4*)&X[(size_t)(m0 + row) * DM + k0 + lc4];
            uint4 at = make_uint4(f32_to_tf32(a.x), f32_to_tf32(a.y),
                                  f32_to_tf32(a.z), f32_to_tf32(a.w));
            *(uint4*)&As[row][lc4] = at;
            float4 b = *(const float4*)&WT[(size_t)(n0 + row) * DM + k0 + lc4];
            uint4 bt = make_uint4(f32_to_tf32(b.x), f32_to_tf32(b.y),
                                  f32_to_tf32(b.z), f32_to_tf32(b.w));
            *(uint4*)&Bs[row][lc4] = bt;
        }
        __syncthreads();

        #pragma unroll
        for (int ks = 0; ks < 4; ++ks) {
            const int kk = ks * 8;
            uint32_t a[2][4];
            #pragma unroll
            for (int i = 0; i < 2; ++i) {
                const int ar = wm * 32 + i * 16 + g;
                a[i][0] = As[ar][kk + t];
                a[i][1] = As[ar + 8][kk + t];
                a[i][2] = As[ar][kk + t + 4];
                a[i][3] = As[ar + 8][kk + t + 4];
            }
            #pragma unroll
            for (int j = 0; j < 8; ++j) {
                const int br = wn * 64 + j * 8 + g;
                uint32_t b0 = Bs[br][kk + t];
                uint32_t b1 = Bs[br][kk + t + 4];
                mma_tf32(acc[0][j], a[0], b0, b1);
                mma_tf32(acc[1][j], a[1], b0, b1);
            }
        }
        __syncthreads();
    }

    // writeback into [B, H, L, DH]
    #pragma unroll
    for (int i = 0; i < 2; ++i) {
        #pragma unroll
        for (int j = 0; j < 8; ++j) {
            const int col  = n0 + wn * 64 + j * 8 + t * 2;
            const int head = col >> 6;
            const int cin  = col & 63;
            const int row0 = m0 + wm * 32 + i * 16 + g;
            // rows row0 (c0,c1) and row0+8 (c2,c3)
            {
                int bb = row0 >> 11, l = row0 & (LEN - 1);
                float* dst = &O[(((size_t)bb * NHEAD + head) * LEN + l) * DH + cin];
                *(float2*)dst = make_float2(acc[i][j][0], acc[i][j][1]);
            }
            {
                int r1 = row0 + 8;
                int bb = r1 >> 11, l = r1 & (LEN - 1);
                float* dst = &O[(((size_t)bb * NHEAD + head) * LEN + l) * DH + cin];
                *(float2*)dst = make_float2(acc[i][j][2], acc[i][j][3]);
            }
        }
    }
}

// ---------------------------------------------------------------------------
// Flash-style attention, single-pass online softmax.
// One block = (b, h, 128 q-rows), 256 threads, TWO threads per q-row
// (each owns 32 of the 64 dims; score halves combined via shfl_xor —
// exact lockstep since fp add is commutative).
// Key mask: loop only over keys < v_len (exp(-1e12)==0 in fp32, identical).
// Query mask: rows >= q_len written as zeros; fully-dead blocks exit early.
// ---------------------------------------------------------------------------
__global__ __launch_bounds__(256) void attn_kernel(
    const int* __restrict__ qlen_p, const int* __restrict__ vlen_p,
    float* __restrict__ Out)
{
    __shared__ float4 k_sm[KTILE * 16];   // [key][16 float4]
    __shared__ float4 v_sm[KTILE * 16];

    const int b = blockIdx.z;
    const int h = blockIdx.y;
    const int tid = threadIdx.x;
    const int row  = tid >> 1;
    const int half = tid & 1;
    const int l = blockIdx.x * ATTN_ROWS + row;
    const int qlen = qlen_p[b];
    const int vlen = vlen_p[b];

    float* outp = &Out[((size_t)b * LEN + l) * DM + h * DH + half * 32];

    if (blockIdx.x * ATTN_ROWS >= qlen) {   // whole block dead
        float4 zero = make_float4(0.f, 0.f, 0.f, 0.f);
        #pragma unroll
        for (int i = 0; i < 8; ++i) *(float4*)&outp[i * 4] = zero;
        return;
    }

    const bool active = (l < qlen);

    const float* qptr  = &g_q[(((size_t)b * NHEAD + h) * LEN + l) * DH + half * 32];
    const float* kbase = &g_k[((size_t)b * NHEAD + h) * LEN * DH];
    const float* vbase = &g_v[((size_t)b * NHEAD + h) * LEN * DH];

    float4 q[8];
    #pragma unroll
    for (int i = 0; i < 8; ++i) {
        if (active) {
            float4 tq = *(const float4*)&qptr[i * 4];
            tq.x *= 0.125f; tq.y *= 0.125f; tq.z *= 0.125f; tq.w *= 0.125f; // 1/sqrt(64)
            q[i] = tq;
        } else {
            q[i] = make_float4(0.f, 0.f, 0.f, 0.f);
        }
    }

    float4 o[8];
    #pragma unroll
    for (int i = 0; i < 8; ++i) o[i] = make_float4(0.f, 0.f, 0.f, 0.f);

    float m = -INFINITY;
    float lsum = 0.f;

    const int ntile = (vlen + KTILE - 1) / KTILE;
    for (int tt = 0; tt < ntile; ++tt) {
        const int k0 = tt * KTILE;
        const int nk = min(KTILE, vlen - k0);

        const float4* kg = (const float4*)&kbase[(size_t)k0 * DH];
        const float4* vg = (const float4*)&vbase[(size_t)k0 * DH];
        #pragma unroll
        for (int i = 0; i < 4; ++i) {
            int idx = tid + i * 256;
            k_sm[idx] = kg[idx];
            v_sm[idx] = vg[idx];
        }
        __syncthreads();

        for (int key = 0; key < nk; ++key) {
            const float4* kr = &k_sm[key * 16 + half * 8];
            float s0 = 0.f, s1 = 0.f, s2 = 0.f, s3 = 0.f;
            #pragma unroll
            for (int i = 0; i < 8; ++i) {
                float4 kv = kr[i];
                s0 = fmaf(q[i].x, kv.x, s0);
                s1 = fmaf(q[i].y, kv.y, s1);
                s2 = fmaf(q[i].z, kv.z, s2);
                s3 = fmaf(q[i].w, kv.w, s3);
            }
            float sp = (s0 + s1) + (s2 + s3);
            float s = sp + __shfl_xor_sync(0xffffffffu, sp, 1);
            if (s > m) {   // new running max (rare after warm-up)
                float corr = __expf(m - s);   // exp(-inf)=0 on first key
                lsum *= corr;
                #pragma unroll
                for (int i = 0; i < 8; ++i) {
                    o[i].x *= corr; o[i].y *= corr;
                    o[i].z *= corr; o[i].w *= corr;
                }
                m = s;
            }
            float p = __expf(s - m);
            lsum += p;
            const float4* vr = &v_sm[key * 16 + half * 8];
            #pragma unroll
            for (int i = 0; i < 8; ++i) {
                float4 vv = vr[i];
                o[i].x = fmaf(p, vv.x, o[i].x);
                o[i].y = fmaf(p, vv.y, o[i].y);
                o[i].z = fmaf(p, vv.z, o[i].z);
                o[i].w = fmaf(p, vv.w, o[i].w);
            }
        }
        __syncthreads();
    }

    if (active) {
        float inv = 1.0f / lsum;
        #pragma unroll
        for (int i = 0; i < 8; ++i) {
            float4 rr = o[i];
            rr.x *= inv; rr.y *= inv; rr.z *= inv; rr.w *= inv;
            *(float4*)&outp[i * 4] = rr;
        }
    } else {
        float4 zero = make_float4(0.f, 0.f, 0.f, 0.f);
        #pragma unroll
        for (int i = 0; i < 8; ++i) *(float4*)&outp[i * 4] = zero;
    }
}

// ---------------------------------------------------------------------------
extern "C" void kernel_launch(void* const* d_in, const int* in_sizes, int n_in,
                              void* d_out, int out_size)
{
    const float* Q_seq = (const float*)d_in[0];
    const float* K_seq = (const float*)d_in[1];
    const float* V_seq = (const float*)d_in[2];
    const int*   q_len = (const int*)d_in[3];
    const int*   v_len = (const int*)d_in[4];
    const float* WQ    = (const float*)d_in[5];
    const float* WK    = (const float*)d_in[6];
    const float* WV    = (const float*)d_in[7];
    float* Out = (float*)d_out;

    // 1) transpose weights once
    dim3 tgrid(DM / 32, DM / 32, 3);
    wt_kernel<<<tgrid, dim3(32, 8)>>>(WQ, WK, WV);

    // 2) tf32 tensor-core projections (mma.sync)
    dim3 pgrid(DM / 128, (BATCH * LEN) / 128, 3);
    proj_mma_kernel<<<pgrid, 256>>>(Q_seq, K_seq, V_seq);

    // 3) attention
    dim3 agrid(LEN / ATTN_ROWS, NHEAD, BATCH);
    attn_kernel<<<agrid, 256>>>(q_len, v_len, Out);
}

// round 9
// speedup vs baseline: 4.4561x; 3.2893x over previous
#include <cuda_runtime.h>
#include <math.h>
#include <stdint.h>

#define NHEAD 16
#define DH    64
#define DM    1024
#define BATCH 2
#define LEN   2048

// Scratch: q,k in [B,H,L,DH]; v stored TRANSPOSED in [B,H,DH,L]; W^T.
__device__ float g_q[(size_t)BATCH * NHEAD * LEN * DH];
__device__ float g_k[(size_t)BATCH * NHEAD * LEN * DH];
__device__ float g_v[(size_t)BATCH * NHEAD * LEN * DH];   // [B][H][DH][LEN]
__device__ float g_wt[(size_t)3 * DM * DM];               // W^T: [n][k]

__device__ __forceinline__ uint32_t f32_to_tf32(float x) {
    uint32_t r;
    asm("cvt.rna.tf32.f32 %0, %1;" : "=r"(r) : "f"(x));
    return r;
}

// m16n8k8 tf32 MMA (sm_80 baseline instruction, tensor core)
__device__ __forceinline__ void mma_tf32(float* c, const uint32_t* a,
                                         uint32_t b0, uint32_t b1) {
    asm volatile(
        "mma.sync.aligned.m16n8k8.row.col.f32.tf32.tf32.f32 "
        "{%0,%1,%2,%3}, {%4,%5,%6,%7}, {%8,%9}, {%0,%1,%2,%3};"
        : "+f"(c[0]), "+f"(c[1]), "+f"(c[2]), "+f"(c[3])
        : "r"(a[0]), "r"(a[1]), "r"(a[2]), "r"(a[3]), "r"(b0), "r"(b1));
}

// ---------------------------------------------------------------------------
// Weight transpose: W[k][n] -> WT[n][k]; z = 0,1,2 for WQ,WK,WV.
// ---------------------------------------------------------------------------
__global__ __launch_bounds__(256) void wt_kernel(
    const float* __restrict__ WQ, const float* __restrict__ WK,
    const float* __restrict__ WV)
{
    __shared__ float t[32][33];
    const float* W = (blockIdx.z == 0) ? WQ : (blockIdx.z == 1) ? WK : WV;
    float* WT = g_wt + (size_t)blockIdx.z * DM * DM;

    const int n0 = blockIdx.x * 32;
    const int k0 = blockIdx.y * 32;
    const int tx = threadIdx.x, ty = threadIdx.y;

    #pragma unroll
    for (int j = 0; j < 4; ++j)
        t[ty + j * 8][tx] = W[(size_t)(k0 + ty + j * 8) * DM + n0 + tx];
    __syncthreads();
    #pragma unroll
    for (int j = 0; j < 4; ++j)
        WT[(size_t)(n0 + ty + j * 8) * DM + k0 + tx] = t[tx][ty + j * 8];
}

// ---------------------------------------------------------------------------
// Projection GEMM on mma.sync tf32. Q/K -> [B,H,L,DH]; V -> [B,H,DH,L].
// ---------------------------------------------------------------------------
#define BK 32
#define KPAD 36

__global__ __launch_bounds__(256) void proj_mma_kernel(
    const float* __restrict__ Q, const float* __restrict__ K,
    const float* __restrict__ V)
{
    __shared__ uint32_t As[128][KPAD];
    __shared__ uint32_t Bs[128][KPAD];

    const int z = blockIdx.z;
    const float* X  = (z == 0) ? Q : (z == 1) ? K : V;
    const float* WT = g_wt + (size_t)z * DM * DM;
    float* O        = (z == 0) ? g_q : (z == 1) ? g_k : g_v;

    const int tid  = threadIdx.x;
    const int wid  = tid >> 5;
    const int lane = tid & 31;
    const int wm   = wid & 3;
    const int wn   = wid >> 2;
    const int m0   = blockIdx.y * 128;
    const int n0   = blockIdx.x * 128;

    const int g = lane >> 2;
    const int t = lane & 3;

    float acc[2][8][4];
    #pragma unroll
    for (int i = 0; i < 2; ++i)
        #pragma unroll
        for (int j = 0; j < 8; ++j)
            #pragma unroll
            for (int c = 0; c < 4; ++c) acc[i][j][c] = 0.f;

    const int lrow = tid >> 3;
    const int lc4  = (tid & 7) * 4;

    for (int k0 = 0; k0 < DM; k0 += BK) {
        #pragma unroll
        for (int r = 0; r < 4; ++r) {
            const int row = lrow + r * 32;
            float4 a = *(const float4*)&X[(size_t)(m0 + row) * DM + k0 + lc4];
            uint4 at = make_uint4(f32_to_tf32(a.x), f32_to_tf32(a.y),
                                  f32_to_tf32(a.z), f32_to_tf32(a.w));
            *(uint4*)&As[row][lc4] = at;
            float4 b = *(const float4*)&WT[(size_t)(n0 + row) * DM + k0 + lc4];
            uint4 bt = make_uint4(f32_to_tf32(b.x), f32_to_tf32(b.y),
                                  f32_to_tf32(b.z), f32_to_tf32(b.w));
            *(uint4*)&Bs[row][lc4] = bt;
        }
        __syncthreads();

        #pragma unroll
        for (int ks = 0; ks < 4; ++ks) {
            const int kk = ks * 8;
            uint32_t a[2][4];
            #pragma unroll
            for (int i = 0; i < 2; ++i) {
                const int ar = wm * 32 + i * 16 + g;
                a[i][0] = As[ar][kk + t];
                a[i][1] = As[ar + 8][kk + t];
                a[i][2] = As[ar][kk + t + 4];
                a[i][3] = As[ar + 8][kk + t + 4];
            }
            #pragma unroll
            for (int j = 0; j < 8; ++j) {
                const int br = wn * 64 + j * 8 + g;
                uint32_t b0 = Bs[br][kk + t];
                uint32_t b1 = Bs[br][kk + t + 4];
                mma_tf32(acc[0][j], a[0], b0, b1);
                mma_tf32(acc[1][j], a[1], b0, b1);
            }
        }
        __syncthreads();
    }

    #pragma unroll
    for (int i = 0; i < 2; ++i) {
        #pragma unroll
        for (int j = 0; j < 8; ++j) {
            const int col  = n0 + wn * 64 + j * 8 + t * 2;
            const int head = col >> 6;
            const int cin  = col & 63;
            #pragma unroll
            for (int rr = 0; rr < 2; ++rr) {
                const int row = m0 + wm * 32 + i * 16 + g + rr * 8;
                const int bb = row >> 11, l = row & (LEN - 1);
                const float v0 = acc[i][j][rr * 2], v1 = acc[i][j][rr * 2 + 1];
                if (z != 2) {
                    float* dst = &O[(((size_t)bb * NHEAD + head) * LEN + l) * DH + cin];
                    *(float2*)dst = make_float2(v0, v1);
                } else {
                    // V^T layout [B][H][DH][LEN]
                    float* base = &O[(((size_t)bb * NHEAD + head) * DH + cin) * LEN + l];
                    base[0]   = v0;
                    base[LEN] = v1;
                }
            }
        }
    }
}

// ---------------------------------------------------------------------------
// Flash attention on mma.sync tf32.
// Block = (b, h, 64 q-rows), 128 threads (4 warps, m16 slab per warp).
// smem: Ks[64][68], VTs[64][68] (V^T: [dh][key]), QPs[64][68] (Q staging,
// then per-warp P buffer). Online softmax on C-fragments.
// ---------------------------------------------------------------------------
#define SPAD 68
#define NEGB 1e30f

__global__ __launch_bounds__(128, 4) void attn_mma_kernel(
    const int* __restrict__ qlen_p, const int* __restrict__ vlen_p,
    float* __restrict__ Out)
{
    extern __shared__ uint32_t dsm[];
    uint32_t* Ks  = dsm;                  // [64][68]
    uint32_t* VTs = dsm + 64 * SPAD;      // [64][68]
    uint32_t* QPs = dsm + 2 * 64 * SPAD;  // [64][68]

    const int b = blockIdx.z;
    const int h = blockIdx.y;
    const int qbase = blockIdx.x * 64;
    const int tid = threadIdx.x;
    const int w = tid >> 5;
    const int lane = tid & 31;
    const int g = lane >> 2;
    const int t = lane & 3;
    const int qlen = qlen_p[b];
    const int vlen = vlen_p[b];

    float* outc = Out + ((size_t)b * LEN) * DM + h * DH;

    if (qbase >= qlen) {   // dead block: zero 64x64 and exit
        float4 zero = make_float4(0.f, 0.f, 0.f, 0.f);
        for (int i = tid; i < 64 * 16; i += 128) {
            int r = i >> 4, c4 = (i & 15) * 4;
            *(float4*)&outc[(size_t)(qbase + r) * DM + c4] = zero;
        }
        return;
    }

    // ---- stage Q (scaled by 1/8, tf32) and load A fragments ----
    const float* qg = g_q + (((size_t)b * NHEAD + h) * LEN + qbase) * DH;
    for (int i = tid; i < 64 * 16; i += 128) {
        int r = i >> 4, c4 = (i & 15) * 4;
        float4 v = *(const float4*)&qg[(size_t)r * DH + c4];
        uint32_t* d = &QPs[r * SPAD + c4];
        d[0] = f32_to_tf32(v.x * 0.125f);
        d[1] = f32_to_tf32(v.y * 0.125f);
        d[2] = f32_to_tf32(v.z * 0.125f);
        d[3] = f32_to_tf32(v.w * 0.125f);
    }
    __syncthreads();

    uint32_t qa[8][4];
    const int mrow = w * 16 + g;
    #pragma unroll
    for (int s = 0; s < 8; ++s) {
        qa[s][0] = QPs[mrow * SPAD + s * 8 + t];
        qa[s][1] = QPs[(mrow + 8) * SPAD + s * 8 + t];
        qa[s][2] = QPs[mrow * SPAD + s * 8 + t + 4];
        qa[s][3] = QPs[(mrow + 8) * SPAD + s * 8 + t + 4];
    }

    float oacc[8][4];
    #pragma unroll
    for (int j = 0; j < 8; ++j)
        #pragma unroll
        for (int c = 0; c < 4; ++c) oacc[j][c] = 0.f;

    float m0 = -NEGB, m1 = -NEGB, l0 = 0.f, l1 = 0.f;

    const float* kg0  = g_k + (((size_t)b * NHEAD + h) * LEN) * DH;
    const float* vtg0 = g_v + (((size_t)b * NHEAD + h) * DH) * LEN;

    const int ntile = (vlen + 63) >> 6;
    for (int kt = 0; kt < ntile; ++kt) {
        const int k0 = kt * 64;
        __syncthreads();   // previous readers of Ks/VTs/QPs done
        // load K tile [key][dh] and V^T tile [dh][key], tf32
        const float* kg  = kg0 + (size_t)k0 * DH;
        const float* vtg = vtg0 + k0;
        for (int i = tid; i < 64 * 16; i += 128) {
            int r = i >> 4, c4 = (i & 15) * 4;
            float4 kv = *(const float4*)&kg[(size_t)r * DH + c4];
            uint32_t* d = &Ks[r * SPAD + c4];
            d[0] = f32_to_tf32(kv.x); d[1] = f32_to_tf32(kv.y);
            d[2] = f32_to_tf32(kv.z); d[3] = f32_to_tf32(kv.w);
            float4 vv = *(const float4*)&vtg[(size_t)r * LEN + c4];
            uint32_t* dv = &VTs[r * SPAD + c4];
            dv[0] = f32_to_tf32(vv.x); dv[1] = f32_to_tf32(vv.y);
            dv[2] = f32_to_tf32(vv.z); dv[3] = f32_to_tf32(vv.w);
        }
        __syncthreads();

        // ---- S = Q K^T ----
        float sa[8][4];
        #pragma unroll
        for (int j = 0; j < 8; ++j)
            #pragma unroll
            for (int c = 0; c < 4; ++c) sa[j][c] = 0.f;
        #pragma unroll
        for (int s = 0; s < 8; ++s)
            #pragma unroll
            for (int j = 0; j < 8; ++j) {
                uint32_t b0 = Ks[(j * 8 + g) * SPAD + s * 8 + t];
                uint32_t b1 = Ks[(j * 8 + g) * SPAD + s * 8 + t + 4];
                mma_tf32(sa[j], qa[s], b0, b1);
            }

        // ---- mask + row max ----
        float tx0 = -NEGB, tx1 = -NEGB;
        #pragma unroll
        for (int j = 0; j < 8; ++j) {
            int key = k0 + j * 8 + 2 * t;
            if (key >= vlen)     { sa[j][0] = -NEGB; sa[j][2] = -NEGB; }
            if (key + 1 >= vlen) { sa[j][1] = -NEGB; sa[j][3] = -NEGB; }
            tx0 = fmaxf(tx0, fmaxf(sa[j][0], sa[j][1]));
            tx1 = fmaxf(tx1, fmaxf(sa[j][2], sa[j][3]));
        }
        tx0 = fmaxf(tx0, __shfl_xor_sync(0xffffffffu, tx0, 1));
        tx0 = fmaxf(tx0, __shfl_xor_sync(0xffffffffu, tx0, 2));
        tx1 = fmaxf(tx1, __shfl_xor_sync(0xffffffffu, tx1, 1));
        tx1 = fmaxf(tx1, __shfl_xor_sync(0xffffffffu, tx1, 2));

        float mn0 = fmaxf(m0, tx0), mn1 = fmaxf(m1, tx1);
        float cr0 = __expf(m0 - mn0), cr1 = __expf(m1 - mn1);
        l0 *= cr0; l1 *= cr1;
        #pragma unroll
        for (int j = 0; j < 8; ++j) {
            oacc[j][0] *= cr0; oacc[j][1] *= cr0;
            oacc[j][2] *= cr1; oacc[j][3] *= cr1;
        }

        // ---- exp, l accumulation, P -> smem (tf32) ----
        #pragma unroll
        for (int j = 0; j < 8; ++j) {
            float p0 = __expf(sa[j][0] - mn0);
            float p1 = __expf(sa[j][1] - mn0);
            float p2 = __expf(sa[j][2] - mn1);
            float p3 = __expf(sa[j][3] - mn1);
            l0 += p0 + p1;  l1 += p2 + p3;
            QPs[mrow * SPAD + j * 8 + 2 * t]           = f32_to_tf32(p0);
            QPs[mrow * SPAD + j * 8 + 2 * t + 1]       = f32_to_tf32(p1);
            QPs[(mrow + 8) * SPAD + j * 8 + 2 * t]     = f32_to_tf32(p2);
            QPs[(mrow + 8) * SPAD + j * 8 + 2 * t + 1] = f32_to_tf32(p3);
        }
        m0 = mn0; m1 = mn1;
        __syncwarp();

        // ---- O += P V ----
        #pragma unroll
        for (int s = 0; s < 8; ++s) {
            uint32_t pa[4];
            pa[0] = QPs[mrow * SPAD + s * 8 + t];
            pa[1] = QPs[(mrow + 8) * SPAD + s * 8 + t];
            pa[2] = QPs[mrow * SPAD + s * 8 + t + 4];
            pa[3] = QPs[(mrow + 8) * SPAD + s * 8 + t + 4];
            #pragma unroll
            for (int j = 0; j < 8; ++j) {
                uint32_t b0 = VTs[(j * 8 + g) * SPAD + s * 8 + t];
                uint32_t b1 = VTs[(j * 8 + g) * SPAD + s * 8 + t + 4];
                mma_tf32(oacc[j], pa, b0, b1);
            }
        }
    }

    // ---- epilogue: reduce l across quad, normalize, masked store ----
    l0 += __shfl_xor_sync(0xffffffffu, l0, 1);
    l0 += __shfl_xor_sync(0xffffffffu, l0, 2);
    l1 += __shfl_xor_sync(0xffffffffu, l1, 1);
    l1 += __shfl_xor_sync(0xffffffffu, l1, 2);
    const float inv0 = 1.0f / l0, inv1 = 1.0f / l1;

    const int r0 = qbase + mrow;
    const int r1 = r0 + 8;
    const bool a0 = (r0 < qlen), a1 = (r1 < qlen);
    #pragma unroll
    for (int j = 0; j < 8; ++j) {
        const int col = j * 8 + 2 * t;
        float2 v0 = a0 ? make_float2(oacc[j][0] * inv0, oacc[j][1] * inv0)
                       : make_float2(0.f, 0.f);
        *(float2*)&outc[(size_t)r0 * DM + col] = v0;
        float2 v1 = a1 ? make_float2(oacc[j][2] * inv1, oacc[j][3] * inv1)
                       : make_float2(0.f, 0.f);
        *(float2*)&outc[(size_t)r1 * DM + col] = v1;
    }
}

// ---------------------------------------------------------------------------
extern "C" void kernel_launch(void* const* d_in, const int* in_sizes, int n_in,
                              void* d_out, int out_size)
{
    const float* Q_seq = (const float*)d_in[0];
    const float* K_seq = (const float*)d_in[1];
    const float* V_seq = (const float*)d_in[2];
    const int*   q_len = (const int*)d_in[3];
    const int*   v_len = (const int*)d_in[4];
    const float* WQ    = (const float*)d_in[5];
    const float* WK    = (const float*)d_in[6];
    const float* WV    = (const float*)d_in[7];
    float* Out = (float*)d_out;

    dim3 tgrid(DM / 32, DM / 32, 3);
    wt_kernel<<<tgrid, dim3(32, 8)>>>(WQ, WK, WV);

    dim3 pgrid(DM / 128, (BATCH * LEN) / 128, 3);
    proj_mma_kernel<<<pgrid, 256>>>(Q_seq, K_seq, V_seq);

    const int smem = 3 * 64 * SPAD * 4;   // 52224 bytes
    static bool attr_set = false;
    if (!attr_set) {
        cudaFuncSetAttribute(attn_mma_kernel,
                             cudaFuncAttributeMaxDynamicSharedMemorySize, smem);
        attr_set = true;
    }
    dim3 agrid(LEN / 64, NHEAD, BATCH);
    attn_mma_kernel<<<agrid, 128, smem>>>(q_len, v_len, Out);
}

// round 10
// speedup vs baseline: 5.0954x; 1.1435x over previous
#include <cuda_runtime.h>
#include <math.h>
#include <stdint.h>

#define NHEAD 16
#define DH    64
#define DM    1024
#define BATCH 2
#define LEN   2048

// Scratch: q,k in [B,H,L,DH]; v stored TRANSPOSED in [B,H,DH,L]; W^T.
__device__ float g_q[(size_t)BATCH * NHEAD * LEN * DH];
__device__ float g_k[(size_t)BATCH * NHEAD * LEN * DH];
__device__ float g_v[(size_t)BATCH * NHEAD * LEN * DH];   // [B][H][DH][LEN]
__device__ float g_wt[(size_t)3 * DM * DM];               // W^T: [n][k]

__device__ __forceinline__ uint32_t f32_to_tf32(float x) {
    uint32_t r;
    asm("cvt.rna.tf32.f32 %0, %1;" : "=r"(r) : "f"(x));
    return r;
}

// m16n8k8 tf32 MMA (sm_80 baseline instruction, tensor core)
__device__ __forceinline__ void mma_tf32(float* c, const uint32_t* a,
                                         uint32_t b0, uint32_t b1) {
    asm volatile(
        "mma.sync.aligned.m16n8k8.row.col.f32.tf32.tf32.f32 "
        "{%0,%1,%2,%3}, {%4,%5,%6,%7}, {%8,%9}, {%0,%1,%2,%3};"
        : "+f"(c[0]), "+f"(c[1]), "+f"(c[2]), "+f"(c[3])
        : "r"(a[0]), "r"(a[1]), "r"(a[2]), "r"(a[3]), "r"(b0), "r"(b1));
}

// ---------------------------------------------------------------------------
// Weight transpose: W[k][n] -> WT[n][k]; z = 0,1,2 for WQ,WK,WV.
// ---------------------------------------------------------------------------
__global__ __launch_bounds__(256) void wt_kernel(
    const float* __restrict__ WQ, const float* __restrict__ WK,
    const float* __restrict__ WV)
{
    __shared__ float t[32][33];
    const float* W = (blockIdx.z == 0) ? WQ : (blockIdx.z == 1) ? WK : WV;
    float* WT = g_wt + (size_t)blockIdx.z * DM * DM;

    const int n0 = blockIdx.x * 32;
    const int k0 = blockIdx.y * 32;
    const int tx = threadIdx.x, ty = threadIdx.y;

    #pragma unroll
    for (int j = 0; j < 4; ++j)
        t[ty + j * 8][tx] = W[(size_t)(k0 + ty + j * 8) * DM + n0 + tx];
    __syncthreads();
    #pragma unroll
    for (int j = 0; j < 4; ++j)
        WT[(size_t)(n0 + ty + j * 8) * DM + k0 + tx] = t[tx][ty + j * 8];
}

// ---------------------------------------------------------------------------
// Projection GEMM on mma.sync tf32. Q/K -> [B,H,L,DH]; V -> [B,H,DH,L].
// Tiles whose 128 rows are all >= len are skipped: attention never reads
// q rows >= qlen nor k/v keys >= vlen (masked / zeroed paths only).
// ---------------------------------------------------------------------------
#define BK 32
#define KPAD 36

__global__ __launch_bounds__(256) void proj_mma_kernel(
    const float* __restrict__ Q, const float* __restrict__ K,
    const float* __restrict__ V,
    const int* __restrict__ qlen_p, const int* __restrict__ vlen_p)
{
    __shared__ uint32_t As[128][KPAD];
    __shared__ uint32_t Bs[128][KPAD];

    const int z = blockIdx.z;
    const int m0 = blockIdx.y * 128;
    const int n0 = blockIdx.x * 128;

    // dead-tile skip (tiles never straddle batches: 2048 % 128 == 0)
    {
        const int bb = m0 >> 11;
        const int l0 = m0 & (LEN - 1);
        const int len = (z == 0) ? qlen_p[bb] : vlen_p[bb];
        if (l0 >= len) return;
    }

    const float* X  = (z == 0) ? Q : (z == 1) ? K : V;
    const float* WT = g_wt + (size_t)z * DM * DM;
    float* O        = (z == 0) ? g_q : (z == 1) ? g_k : g_v;

    const int tid  = threadIdx.x;
    const int wid  = tid >> 5;
    const int lane = tid & 31;
    const int wm   = wid & 3;
    const int wn   = wid >> 2;

    const int g = lane >> 2;
    const int t = lane & 3;

    float acc[2][8][4];
    #pragma unroll
    for (int i = 0; i < 2; ++i)
        #pragma unroll
        for (int j = 0; j < 8; ++j)
            #pragma unroll
            for (int c = 0; c < 4; ++c) acc[i][j][c] = 0.f;

    const int lrow = tid >> 3;
    const int lc4  = (tid & 7) * 4;

    for (int k0 = 0; k0 < DM; k0 += BK) {
        #pragma unroll
        for (int r = 0; r < 4; ++r) {
            const int row = lrow + r * 32;
            float4 a = *(const float4*)&X[(size_t)(m0 + row) * DM + k0 + lc4];
            uint4 at = make_uint4(f32_to_tf32(a.x), f32_to_tf32(a.y),
                                  f32_to_tf32(a.z), f32_to_tf32(a.w));
            *(uint4*)&As[row][lc4] = at;
            float4 b = *(const float4*)&WT[(size_t)(n0 + row) * DM + k0 + lc4];
            uint4 bt = make_uint4(f32_to_tf32(b.x), f32_to_tf32(b.y),
                                  f32_to_tf32(b.z), f32_to_tf32(b.w));
            *(uint4*)&Bs[row][lc4] = bt;
        }
        __syncthreads();

        #pragma unroll
        for (int ks = 0; ks < 4; ++ks) {
            const int kk = ks * 8;
            uint32_t a[2][4];
            #pragma unroll
            for (int i = 0; i < 2; ++i) {
                const int ar = wm * 32 + i * 16 + g;
                a[i][0] = As[ar][kk + t];
                a[i][1] = As[ar + 8][kk + t];
                a[i][2] = As[ar][kk + t + 4];
                a[i][3] = As[ar + 8][kk + t + 4];
            }
            #pragma unroll
            for (int j = 0; j < 8; ++j) {
                const int br = wn * 64 + j * 8 + g;
                uint32_t b0 = Bs[br][kk + t];
                uint32_t b1 = Bs[br][kk + t + 4];
                mma_tf32(acc[0][j], a[0], b0, b1);
                mma_tf32(acc[1][j], a[1], b0, b1);
            }
        }
        __syncthreads();
    }

    #pragma unroll
    for (int i = 0; i < 2; ++i) {
        #pragma unroll
        for (int j = 0; j < 8; ++j) {
            const int col  = n0 + wn * 64 + j * 8 + t * 2;
            const int head = col >> 6;
            const int cin  = col & 63;
            #pragma unroll
            for (int rr = 0; rr < 2; ++rr) {
                const int row = m0 + wm * 32 + i * 16 + g + rr * 8;
                const int bb = row >> 11, l = row & (LEN - 1);
                const float v0 = acc[i][j][rr * 2], v1 = acc[i][j][rr * 2 + 1];
                if (z != 2) {
                    float* dst = &O[(((size_t)bb * NHEAD + head) * LEN + l) * DH + cin];
                    *(float2*)dst = make_float2(v0, v1);
                } else {
                    // V^T layout [B][H][DH][LEN]
                    float* base = &O[(((size_t)bb * NHEAD + head) * DH + cin) * LEN + l];
                    base[0]   = v0;
                    base[LEN] = v1;
                }
            }
        }
    }
}

// ---------------------------------------------------------------------------
// Flash attention on mma.sync tf32.
// Block = (b, h, 128 q-rows), 128 threads (4 warps). Each K/V^T tile is
// loaded once and used for TWO 64-row q halves (amortized fill).
// smem: Qs[128][68] (tf32 Q, resident), Ks[64][68], VTs[64][68],
//       Ps[64][68] (per-warp P slabs). 85 KB -> 2 CTA/SM.
// ---------------------------------------------------------------------------
#define QROWS 128
#define SPAD 68
#define NEGB 1e30f

__global__ __launch_bounds__(128, 2) void attn_mma_kernel(
    const int* __restrict__ qlen_p, const int* __restrict__ vlen_p,
    float* __restrict__ Out)
{
    extern __shared__ uint32_t dsm[];
    uint32_t* Qs  = dsm;                        // [128][68]
    uint32_t* Ks  = dsm + QROWS * SPAD;         // [64][68]
    uint32_t* VTs = Ks + 64 * SPAD;             // [64][68]
    uint32_t* Ps  = VTs + 64 * SPAD;            // [64][68]

    const int b = blockIdx.z;
    const int h = blockIdx.y;
    const int qbase = blockIdx.x * QROWS;
    const int tid = threadIdx.x;
    const int w = tid >> 5;
    const int lane = tid & 31;
    const int g = lane >> 2;
    const int t = lane & 3;
    const int qlen = qlen_p[b];
    const int vlen = vlen_p[b];

    float* outc = Out + ((size_t)b * LEN) * DM + h * DH;

    if (qbase >= qlen) {   // dead block: zero 128x64 and exit
        float4 zero = make_float4(0.f, 0.f, 0.f, 0.f);
        for (int i = tid; i < QROWS * 16; i += 128) {
            int r = i >> 4, c4 = (i & 15) * 4;
            *(float4*)&outc[(size_t)(qbase + r) * DM + c4] = zero;
        }
        return;
    }

    // ---- stage Q (scaled by 1/8, tf32), resident for whole kernel ----
    const float* qg = g_q + (((size_t)b * NHEAD + h) * LEN + qbase) * DH;
    for (int i = tid; i < QROWS * 16; i += 128) {
        int r = i >> 4, c4 = (i & 15) * 4;
        float4 v = *(const float4*)&qg[(size_t)r * DH + c4];
        uint32_t* d = &Qs[r * SPAD + c4];
        d[0] = f32_to_tf32(v.x * 0.125f);
        d[1] = f32_to_tf32(v.y * 0.125f);
        d[2] = f32_to_tf32(v.z * 0.125f);
        d[3] = f32_to_tf32(v.w * 0.125f);
    }

    const int mrow = w * 16 + g;   // row within a 64-row half (P slab row)

    float oacc[2][8][4];
    float m[2][2], l[2][2];
    #pragma unroll
    for (int hf = 0; hf < 2; ++hf) {
        m[hf][0] = -NEGB; m[hf][1] = -NEGB;
        l[hf][0] = 0.f;   l[hf][1] = 0.f;
        #pragma unroll
        for (int j = 0; j < 8; ++j)
            #pragma unroll
            for (int c = 0; c < 4; ++c) oacc[hf][j][c] = 0.f;
    }

    const float* kg0  = g_k + (((size_t)b * NHEAD + h) * LEN) * DH;
    const float* vtg0 = g_v + (((size_t)b * NHEAD + h) * DH) * LEN;

    const int ntile = (vlen + 63) >> 6;
    for (int kt = 0; kt < ntile; ++kt) {
        const int k0 = kt * 64;
        __syncthreads();   // previous readers of Ks/VTs done (also covers Qs stage)
        const float* kg  = kg0 + (size_t)k0 * DH;
        const float* vtg = vtg0 + k0;
        for (int i = tid; i < 64 * 16; i += 128) {
            int r = i >> 4, c4 = (i & 15) * 4;
            float4 kv = *(const float4*)&kg[(size_t)r * DH + c4];
            uint32_t* d = &Ks[r * SPAD + c4];
            d[0] = f32_to_tf32(kv.x); d[1] = f32_to_tf32(kv.y);
            d[2] = f32_to_tf32(kv.z); d[3] = f32_to_tf32(kv.w);
            float4 vv = *(const float4*)&vtg[(size_t)r * LEN + c4];
            uint32_t* dv = &VTs[r * SPAD + c4];
            dv[0] = f32_to_tf32(vv.x); dv[1] = f32_to_tf32(vv.y);
            dv[2] = f32_to_tf32(vv.z); dv[3] = f32_to_tf32(vv.w);
        }
        __syncthreads();

        #pragma unroll
        for (int hf = 0; hf < 2; ++hf) {
            const int hrow = hf * 64 + mrow;

            // ---- Q fragments for this half (from resident Qs) ----
            uint32_t qa[8][4];
            #pragma unroll
            for (int s = 0; s < 8; ++s) {
                qa[s][0] = Qs[hrow * SPAD + s * 8 + t];
                qa[s][1] = Qs[(hrow + 8) * SPAD + s * 8 + t];
                qa[s][2] = Qs[hrow * SPAD + s * 8 + t + 4];
                qa[s][3] = Qs[(hrow + 8) * SPAD + s * 8 + t + 4];
            }

            // ---- S = Q K^T ----
            float sa[8][4];
            #pragma unroll
            for (int j = 0; j < 8; ++j)
                #pragma unroll
                for (int c = 0; c < 4; ++c) sa[j][c] = 0.f;
            #pragma unroll
            for (int s = 0; s < 8; ++s)
                #pragma unroll
                for (int j = 0; j < 8; ++j) {
                    uint32_t b0 = Ks[(j * 8 + g) * SPAD + s * 8 + t];
                    uint32_t b1 = Ks[(j * 8 + g) * SPAD + s * 8 + t + 4];
                    mma_tf32(sa[j], qa[s], b0, b1);
                }

            // ---- mask + row max ----
            float tx0 = -NEGB, tx1 = -NEGB;
            #pragma unroll
            for (int j = 0; j < 8; ++j) {
                int key = k0 + j * 8 + 2 * t;
                if (key >= vlen)     { sa[j][0] = -NEGB; sa[j][2] = -NEGB; }
                if (key + 1 >= vlen) { sa[j][1] = -NEGB; sa[j][3] = -NEGB; }
                tx0 = fmaxf(tx0, fmaxf(sa[j][0], sa[j][1]));
                tx1 = fmaxf(tx1, fmaxf(sa[j][2], sa[j][3]));
            }
            tx0 = fmaxf(tx0, __shfl_xor_sync(0xffffffffu, tx0, 1));
            tx0 = fmaxf(tx0, __shfl_xor_sync(0xffffffffu, tx0, 2));
            tx1 = fmaxf(tx1, __shfl_xor_sync(0xffffffffu, tx1, 1));
            tx1 = fmaxf(tx1, __shfl_xor_sync(0xffffffffu, tx1, 2));

            float mn0 = fmaxf(m[hf][0], tx0), mn1 = fmaxf(m[hf][1], tx1);
            float cr0 = __expf(m[hf][0] - mn0), cr1 = __expf(m[hf][1] - mn1);
            l[hf][0] *= cr0; l[hf][1] *= cr1;
            #pragma unroll
            for (int j = 0; j < 8; ++j) {
                oacc[hf][j][0] *= cr0; oacc[hf][j][1] *= cr0;
                oacc[hf][j][2] *= cr1; oacc[hf][j][3] *= cr1;
            }

            // ---- exp, l accumulation, P -> smem (tf32, per-warp slab) ----
            #pragma unroll
            for (int j = 0; j < 8; ++j) {
                float p0 = __expf(sa[j][0] - mn0);
                float p1 = __expf(sa[j][1] - mn0);
                float p2 = __expf(sa[j][2] - mn1);
                float p3 = __expf(sa[j][3] - mn1);
                l[hf][0] += p0 + p1;  l[hf][1] += p2 + p3;
                Ps[mrow * SPAD + j * 8 + 2 * t]           = f32_to_tf32(p0);
                Ps[mrow * SPAD + j * 8 + 2 * t + 1]       = f32_to_tf32(p1);
                Ps[(mrow + 8) * SPAD + j * 8 + 2 * t]     = f32_to_tf32(p2);
                Ps[(mrow + 8) * SPAD + j * 8 + 2 * t + 1] = f32_to_tf32(p3);
            }
            m[hf][0] = mn0; m[hf][1] = mn1;
            __syncwarp();

            // ---- O += P V ----
            #pragma unroll
            for (int s = 0; s < 8; ++s) {
                uint32_t pa[4];
                pa[0] = Ps[mrow * SPAD + s * 8 + t];
                pa[1] = Ps[(mrow + 8) * SPAD + s * 8 + t];
                pa[2] = Ps[mrow * SPAD + s * 8 + t + 4];
                pa[3] = Ps[(mrow + 8) * SPAD + s * 8 + t + 4];
                #pragma unroll
                for (int j = 0; j < 8; ++j) {
                    uint32_t b0 = VTs[(j * 8 + g) * SPAD + s * 8 + t];
                    uint32_t b1 = VTs[(j * 8 + g) * SPAD + s * 8 + t + 4];
                    mma_tf32(oacc[hf][j], pa, b0, b1);
                }
            }
            __syncwarp();   // P slab reads done before next half overwrites
        }
    }

    // ---- epilogue: reduce l across quad, normalize, masked store ----
    #pragma unroll
    for (int hf = 0; hf < 2; ++hf) {
        float l0 = l[hf][0], l1 = l[hf][1];
        l0 += __shfl_xor_sync(0xffffffffu, l0, 1);
        l0 += __shfl_xor_sync(0xffffffffu, l0, 2);
        l1 += __shfl_xor_sync(0xffffffffu, l1, 1);
        l1 += __shfl_xor_sync(0xffffffffu, l1, 2);
        const float inv0 = 1.0f / l0, inv1 = 1.0f / l1;

        const int r0 = qbase + hf * 64 + mrow;
        const int r1 = r0 + 8;
        const bool a0 = (r0 < qlen), a1 = (r1 < qlen);
        #pragma unroll
        for (int j = 0; j < 8; ++j) {
            const int col = j * 8 + 2 * t;
            float2 v0 = a0 ? make_float2(oacc[hf][j][0] * inv0, oacc[hf][j][1] * inv0)
                           : make_float2(0.f, 0.f);
            *(float2*)&outc[(size_t)r0 * DM + col] = v0;
            float2 v1 = a1 ? make_float2(oacc[hf][j][2] * inv1, oacc[hf][j][3] * inv1)
                           : make_float2(0.f, 0.f);
            *(float2*)&outc[(size_t)r1 * DM + col] = v1;
        }
    }
}

// ---------------------------------------------------------------------------
extern "C" void kernel_launch(void* const* d_in, const int* in_sizes, int n_in,
                              void* d_out, int out_size)
{
    const float* Q_seq = (const float*)d_in[0];
    const float* K_seq = (const float*)d_in[1];
    const float* V_seq = (const float*)d_in[2];
    const int*   q_len = (const int*)d_in[3];
    const int*   v_len = (const int*)d_in[4];
    const float* WQ    = (const float*)d_in[5];
    const float* WK    = (const float*)d_in[6];
    const float* WV    = (const float*)d_in[7];
    float* Out = (float*)d_out;

    dim3 tgrid(DM / 32, DM / 32, 3);
    wt_kernel<<<tgrid, dim3(32, 8)>>>(WQ, WK, WV);

    dim3 pgrid(DM / 128, (BATCH * LEN) / 128, 3);
    proj_mma_kernel<<<pgrid, 256>>>(Q_seq, K_seq, V_seq, q_len, v_len);

    const int smem = (QROWS + 3 * 64) * SPAD * 4;   // 87040 bytes
    static bool attr_set = false;
    if (!attr_set) {
        cudaFuncSetAttribute(attn_mma_kernel,
                             cudaFuncAttributeMaxDynamicSharedMemorySize, smem);
        attr_set = true;
    }
    dim3 agrid(LEN / QROWS, NHEAD, BATCH);
    attn_mma_kernel<<<agrid, 128, smem>>>(q_len, v_len, Out);
}

// round 14
// speedup vs baseline: 5.3057x; 1.0413x over previous
#include <cuda_runtime.h>
#include <math.h>
#include <stdint.h>

#define NHEAD 16
#define DH    64
#define DM    1024
#define BATCH 2
#define LEN   2048

// Scratch (values stored as tf32-rounded f32 bits, ready for mma.sync):
// q,k in [B,H,L,DH] (q pre-scaled by 1/8); v TRANSPOSED in [B,H,DH,L]; W^T.
__device__ float g_q[(size_t)BATCH * NHEAD * LEN * DH];
__device__ float g_k[(size_t)BATCH * NHEAD * LEN * DH];
__device__ float g_v[(size_t)BATCH * NHEAD * LEN * DH];   // [B][H][DH][LEN]
__device__ float g_wt[(size_t)3 * DM * DM];               // tf32(W^T): [n][k]

__device__ __forceinline__ uint32_t f32_to_tf32(float x) {
    uint32_t r;
    asm("cvt.rna.tf32.f32 %0, %1;" : "=r"(r) : "f"(x));
    return r;
}

// m16n8k8 tf32 MMA (sm_80 baseline instruction, tensor core)
__device__ __forceinline__ void mma_tf32(float* c, const uint32_t* a,
                                         uint32_t b0, uint32_t b1) {
    asm volatile(
        "mma.sync.aligned.m16n8k8.row.col.f32.tf32.tf32.f32 "
        "{%0,%1,%2,%3}, {%4,%5,%6,%7}, {%8,%9}, {%0,%1,%2,%3};"
        : "+f"(c[0]), "+f"(c[1]), "+f"(c[2]), "+f"(c[3])
        : "r"(a[0]), "r"(a[1]), "r"(a[2]), "r"(a[3]), "r"(b0), "r"(b1));
}

#define CP_ASYNC16(dst_smem, src_gmem) \
    asm volatile("cp.async.cg.shared.global [%0], [%1], 16;" \
                 :: "r"(dst_smem), "l"(src_gmem))
#define CP_COMMIT() asm volatile("cp.async.commit_group;" ::: "memory")
#define CP_WAIT1()  asm volatile("cp.async.wait_group 1;" ::: "memory")
#define CP_WAIT0()  asm volatile("cp.async.wait_group 0;" ::: "memory")

// ---------------------------------------------------------------------------
// Weight transpose + tf32 pre-round: W[k][n] -> tf32(W^T)[n][k].
// ---------------------------------------------------------------------------
__global__ __launch_bounds__(256) void wt_kernel(
    const float* __restrict__ WQ, const float* __restrict__ WK,
    const float* __restrict__ WV)
{
    __shared__ float t[32][33];
    const float* W = (blockIdx.z == 0) ? WQ : (blockIdx.z == 1) ? WK : WV;
    float* WT = g_wt + (size_t)blockIdx.z * DM * DM;

    const int n0 = blockIdx.x * 32;
    const int k0 = blockIdx.y * 32;
    const int tx = threadIdx.x, ty = threadIdx.y;

    #pragma unroll
    for (int j = 0; j < 4; ++j)
        t[ty + j * 8][tx] = W[(size_t)(k0 + ty + j * 8) * DM + n0 + tx];
    __syncthreads();
    #pragma unroll
    for (int j = 0; j < 4; ++j)
        WT[(size_t)(n0 + ty + j * 8) * DM + k0 + tx] =
            __uint_as_float(f32_to_tf32(t[tx][ty + j * 8]));
}

// ---------------------------------------------------------------------------
// Projection GEMM on mma.sync tf32. Writes tf32-rounded outputs:
// Q (x1/8) / K -> [B,H,L,DH]; V -> [B,H,DH,L]. Dead tiles skipped.
// ---------------------------------------------------------------------------
#define BK 32
#define KPAD 36

__global__ __launch_bounds__(256) void proj_mma_kernel(
    const float* __restrict__ Q, const float* __restrict__ K,
    const float* __restrict__ V,
    const int* __restrict__ qlen_p, const int* __restrict__ vlen_p)
{
    __shared__ uint32_t As[128][KPAD];
    __shared__ uint32_t Bs[128][KPAD];

    const int z = blockIdx.z;
    const int m0 = blockIdx.y * 128;
    const int n0 = blockIdx.x * 128;

    {   // dead-tile skip (tiles never straddle batches)
        const int bb = m0 >> 11;
        const int l0 = m0 & (LEN - 1);
        const int len = (z == 0) ? qlen_p[bb] : vlen_p[bb];
        if (l0 >= len) return;
    }

    const float* X  = (z == 0) ? Q : (z == 1) ? K : V;
    const float* WT = g_wt + (size_t)z * DM * DM;
    float* O        = (z == 0) ? g_q : (z == 1) ? g_k : g_v;

    const int tid  = threadIdx.x;
    const int wid  = tid >> 5;
    const int lane = tid & 31;
    const int wm   = wid & 3;
    const int wn   = wid >> 2;
    const int g = lane >> 2;
    const int t = lane & 3;

    float acc[2][8][4];
    #pragma unroll
    for (int i = 0; i < 2; ++i)
        #pragma unroll
        for (int j = 0; j < 8; ++j)
            #pragma unroll
            for (int c = 0; c < 4; ++c) acc[i][j][c] = 0.f;

    const int lrow = tid >> 3;
    const int lc4  = (tid & 7) * 4;

    for (int k0 = 0; k0 < DM; k0 += BK) {
        #pragma unroll
        for (int r = 0; r < 4; ++r) {
            const int row = lrow + r * 32;
            float4 a = *(const float4*)&X[(size_t)(m0 + row) * DM + k0 + lc4];
            uint4 at = make_uint4(f32_to_tf32(a.x), f32_to_tf32(a.y),
                                  f32_to_tf32(a.z), f32_to_tf32(a.w));
            *(uint4*)&As[row][lc4] = at;
            // W^T is pre-rounded to tf32: raw copy
            uint4 bt = *(const uint4*)&WT[(size_t)(n0 + row) * DM + k0 + lc4];
            *(uint4*)&Bs[row][lc4] = bt;
        }
        __syncthreads();

        #pragma unroll
        for (int ks = 0; ks < 4; ++ks) {
            const int kk = ks * 8;
            uint32_t a[2][4];
            #pragma unroll
            for (int i = 0; i < 2; ++i) {
                const int ar = wm * 32 + i * 16 + g;
                a[i][0] = As[ar][kk + t];
                a[i][1] = As[ar + 8][kk + t];
                a[i][2] = As[ar][kk + t + 4];
                a[i][3] = As[ar + 8][kk + t + 4];
            }
            #pragma unroll
            for (int j = 0; j < 8; ++j) {
                const int br = wn * 64 + j * 8 + g;
                uint32_t b0 = Bs[br][kk + t];
                uint32_t b1 = Bs[br][kk + t + 4];
                mma_tf32(acc[0][j], a[0], b0, b1);
                mma_tf32(acc[1][j], a[1], b0, b1);
            }
        }
        __syncthreads();
    }

    const float scale = (z == 0) ? 0.125f : 1.0f;   // fold 1/sqrt(DH) into Q
    #pragma unroll
    for (int i = 0; i < 2; ++i) {
        #pragma unroll
        for (int j = 0; j < 8; ++j) {
            const int col  = n0 + wn * 64 + j * 8 + t * 2;
            const int head = col >> 6;
            const int cin  = col & 63;
            #pragma unroll
            for (int rr = 0; rr < 2; ++rr) {
                const int row = m0 + wm * 32 + i * 16 + g + rr * 8;
                const int bb = row >> 11, l = row & (LEN - 1);
                const float v0 = __uint_as_float(f32_to_tf32(acc[i][j][rr * 2] * scale));
                const float v1 = __uint_as_float(f32_to_tf32(acc[i][j][rr * 2 + 1] * scale));
                if (z != 2) {
                    float* dst = &O[(((size_t)bb * NHEAD + head) * LEN + l) * DH + cin];
                    *(float2*)dst = make_float2(v0, v1);
                } else {
                    float* base = &O[(((size_t)bb * NHEAD + head) * DH + cin) * LEN + l];
                    base[0]   = v0;
                    base[LEN] = v1;
                }
            }
        }
    }
}

// ---------------------------------------------------------------------------
// Flash attention on mma.sync tf32 with cp.async double-buffered K/V^T.
// Block = (b, h, 64 q-rows), 128 threads (4 warps, m16 slab per warp).
// All operands pre-rounded to tf32 in gmem -> loads are pure byte copies.
// smem: Qs[64][68], Kb[2][64][68], Vb[2][64][68], Ps[64][68] = 104.4 KB.
// ---------------------------------------------------------------------------
#define SPAD 68
#define TILEW (64 * SPAD)
#define NEGB 1e30f

__global__ __launch_bounds__(128, 2) void attn_mma_kernel(
    const int* __restrict__ qlen_p, const int* __restrict__ vlen_p,
    float* __restrict__ Out)
{
    extern __shared__ uint32_t dsm[];
    uint32_t* Qs = dsm;                 // [64][68]
    uint32_t* Kb0 = dsm + TILEW;        // double-buffered K
    uint32_t* Kb1 = dsm + 2 * TILEW;
    uint32_t* Vb0 = dsm + 3 * TILEW;    // double-buffered V^T
    uint32_t* Vb1 = dsm + 4 * TILEW;
    uint32_t* Ps  = dsm + 5 * TILEW;    // [64][68]

    const int b = blockIdx.z;
    const int h = blockIdx.y;
    const int qbase = blockIdx.x * 64;
    const int tid = threadIdx.x;
    const int w = tid >> 5;
    const int lane = tid & 31;
    const int g = lane >> 2;
    const int t = lane & 3;
    const int qlen = qlen_p[b];
    const int vlen = vlen_p[b];

    float* outc = Out + ((size_t)b * LEN) * DM + h * DH;

    if (qbase >= qlen) {   // dead block: zero 64x64 and exit
        float4 zero = make_float4(0.f, 0.f, 0.f, 0.f);
        for (int i = tid; i < 64 * 16; i += 128) {
            int r = i >> 4, c4 = (i & 15) * 4;
            *(float4*)&outc[(size_t)(qbase + r) * DM + c4] = zero;
        }
        return;
    }

    const float* qg   = g_q + (((size_t)b * NHEAD + h) * LEN + qbase) * DH;
    const float* kg0  = g_k + (((size_t)b * NHEAD + h) * LEN) * DH;
    const float* vtg0 = g_v + (((size_t)b * NHEAD + h) * DH) * LEN;

    const uint32_t smem_base = (uint32_t)__cvta_generic_to_shared(dsm);
    const int ntile = (vlen + 63) >> 6;

    // per-thread copy coords: 1024 float4 per 64x64 tile / 128 threads = 8
    const int crow = tid >> 4;          // base row 0..7 (stride 8)
    const int cc4  = (tid & 15) * 4;    // word col 0..60

    // ---- prologue: Q + tile0 (group A), tile1 (group B) ----
    {
        #pragma unroll
        for (int i = 0; i < 8; ++i) {
            int r = crow + i * 8;
            CP_ASYNC16(smem_base + (r * SPAD + cc4) * 4, qg + (size_t)r * DH + cc4);
        }
        const float* kg  = kg0;
        const float* vtg = vtg0;
        #pragma unroll
        for (int i = 0; i < 8; ++i) {
            int r = crow + i * 8;
            CP_ASYNC16(smem_base + (TILEW + r * SPAD + cc4) * 4, kg + (size_t)r * DH + cc4);
            CP_ASYNC16(smem_base + (3 * TILEW + r * SPAD + cc4) * 4, vtg + (size_t)r * LEN + cc4);
        }
        CP_COMMIT();
        if (ntile > 1) {
            kg  = kg0 + (size_t)64 * DH;
            vtg = vtg0 + 64;
            #pragma unroll
            for (int i = 0; i < 8; ++i) {
                int r = crow + i * 8;
                CP_ASYNC16(smem_base + (2 * TILEW + r * SPAD + cc4) * 4, kg + (size_t)r * DH + cc4);
                CP_ASYNC16(smem_base + (4 * TILEW + r * SPAD + cc4) * 4, vtg + (size_t)r * LEN + cc4);
            }
            CP_COMMIT();
        }
    }

    const int mrow = w * 16 + g;

    float oacc[8][4];
    #pragma unroll
    for (int j = 0; j < 8; ++j)
        #pragma unroll
        for (int c = 0; c < 4; ++c) oacc[j][c] = 0.f;
    float m0 = -NEGB, m1 = -NEGB, l0 = 0.f, l1 = 0.f;

    for (int kt = 0; kt < ntile; ++kt) {
        if (kt + 1 < ntile) { CP_WAIT1(); } else { CP_WAIT0(); }
        __syncthreads();

        uint32_t* Ks  = (kt & 1) ? Kb1 : Kb0;
        uint32_t* VTs = (kt & 1) ? Vb1 : Vb0;
        const int k0 = kt * 64;

        // ---- Q fragments (resident Qs) ----
        uint32_t qa[8][4];
        #pragma unroll
        for (int s = 0; s < 8; ++s) {
            qa[s][0] = Qs[mrow * SPAD + s * 8 + t];
            qa[s][1] = Qs[(mrow + 8) * SPAD + s * 8 + t];
            qa[s][2] = Qs[mrow * SPAD + s * 8 + t + 4];
            qa[s][3] = Qs[(mrow + 8) * SPAD + s * 8 + t + 4];
        }

        // ---- S = Q K^T ----
        float sa[8][4];
        #pragma unroll
        for (int j = 0; j < 8; ++j)
            #pragma unroll
            for (int c = 0; c < 4; ++c) sa[j][c] = 0.f;
        #pragma unroll
        for (int s = 0; s < 8; ++s)
            #pragma unroll
            for (int j = 0; j < 8; ++j) {
                uint32_t b0 = Ks[(j * 8 + g) * SPAD + s * 8 + t];
                uint32_t b1 = Ks[(j * 8 + g) * SPAD + s * 8 + t + 4];
                mma_tf32(sa[j], qa[s], b0, b1);
            }

        // ---- mask + row max ----
        float tx0 = -NEGB, tx1 = -NEGB;
        #pragma unroll
        for (int j = 0; j < 8; ++j) {
            int key = k0 + j * 8 + 2 * t;
            if (key >= vlen)     { sa[j][0] = -NEGB; sa[j][2] = -NEGB; }
            if (key + 1 >= vlen) { sa[j][1] = -NEGB; sa[j][3] = -NEGB; }
            tx0 = fmaxf(tx0, fmaxf(sa[j][0], sa[j][1]));
            tx1 = fmaxf(tx1, fmaxf(sa[j][2], sa[j][3]));
        }
        tx0 = fmaxf(tx0, __shfl_xor_sync(0xffffffffu, tx0, 1));
        tx0 = fmaxf(tx0, __shfl_xor_sync(0xffffffffu, tx0, 2));
        tx1 = fmaxf(tx1, __shfl_xor_sync(0xffffffffu, tx1, 1));
        tx1 = fmaxf(tx1, __shfl_xor_sync(0xffffffffu, tx1, 2));

        float mn0 = fmaxf(m0, tx0), mn1 = fmaxf(m1, tx1);
        float cr0 = __expf(m0 - mn0), cr1 = __expf(m1 - mn1);
        l0 *= cr0; l1 *= cr1;
        #pragma unroll
        for (int j = 0; j < 8; ++j) {
            oacc[j][0] *= cr0; oacc[j][1] *= cr0;
            oacc[j][2] *= cr1; oacc[j][3] *= cr1;
        }

        // ---- exp, l accumulation, P -> smem (tf32) ----
        #pragma unroll
        for (int j = 0; j < 8; ++j) {
            float p0 = __expf(sa[j][0] - mn0);
            float p1 = __expf(sa[j][1] - mn0);
            float p2 = __expf(sa[j][2] - mn1);
            float p3 = __expf(sa[j][3] - mn1);
            l0 += p0 + p1;  l1 += p2 + p3;
            Ps[mrow * SPAD + j * 8 + 2 * t]           = f32_to_tf32(p0);
            Ps[mrow * SPAD + j * 8 + 2 * t + 1]       = f32_to_tf32(p1);
            Ps[(mrow + 8) * SPAD + j * 8 + 2 * t]     = f32_to_tf32(p2);
            Ps[(mrow + 8) * SPAD + j * 8 + 2 * t + 1] = f32_to_tf32(p3);
        }
        m0 = mn0; m1 = mn1;
        __syncwarp();

        // ---- O += P V ----
        #pragma unroll
        for (int s = 0; s < 8; ++s) {
            uint32_t pa[4];
            pa[0] = Ps[mrow * SPAD + s * 8 + t];
            pa[1] = Ps[(mrow + 8) * SPAD + s * 8 + t];
            pa[2] = Ps[mrow * SPAD + s * 8 + t + 4];
            pa[3] = Ps[(mrow + 8) * SPAD + s * 8 + t + 4];
            #pragma unroll
            for (int j = 0; j < 8; ++j) {
                uint32_t b0 = VTs[(j * 8 + g) * SPAD + s * 8 + t];
                uint32_t b1 = VTs[(j * 8 + g) * SPAD + s * 8 + t + 4];
                mma_tf32(oacc[j], pa, b0, b1);
            }
        }
        __syncthreads();

        // ---- prefetch tile kt+2 into the buffer just freed ----
        if (kt + 2 < ntile) {
            const int kn = (kt + 2) * 64;
            const float* kg  = kg0 + (size_t)kn * DH;
            const float* vtg = vtg0 + kn;
            const uint32_t koff = ((kt & 1) ? 2u : 1u) * TILEW;
            const uint32_t voff = ((kt & 1) ? 4u : 3u) * TILEW;
            #pragma unroll
            for (int i = 0; i < 8; ++i) {
                int r = crow + i * 8;
                CP_ASYNC16(smem_base + (koff + r * SPAD + cc4) * 4, kg + (size_t)r * DH + cc4);
                CP_ASYNC16(smem_base + (voff + r * SPAD + cc4) * 4, vtg + (size_t)r * LEN + cc4);
            }
            CP_COMMIT();
        }
    }

    // ---- epilogue: reduce l across quad, normalize, masked store ----
    l0 += __shfl_xor_sync(0xffffffffu, l0, 1);
    l0 += __shfl_xor_sync(0xffffffffu, l0, 2);
    l1 += __shfl_xor_sync(0xffffffffu, l1, 1);
    l1 += __shfl_xor_sync(0xffffffffu, l1, 2);
    const float inv0 = 1.0f / l0, inv1 = 1.0f / l1;

    const int r0 = qbase + mrow;
    const int r1 = r0 + 8;
    const bool a0 = (r0 < qlen), a1 = (r1 < qlen);
    #pragma unroll
    for (int j = 0; j < 8; ++j) {
        const int col = j * 8 + 2 * t;
        float2 v0 = a0 ? make_float2(oacc[j][0] * inv0, oacc[j][1] * inv0)
                       : make_float2(0.f, 0.f);
        *(float2*)&outc[(size_t)r0 * DM + col] = v0;
        float2 v1 = a1 ? make_float2(oacc[j][2] * inv1, oacc[j][3] * inv1)
                       : make_float2(0.f, 0.f);
        *(float2*)&outc[(size_t)r1 * DM + col] = v1;
    }
}

// ---------------------------------------------------------------------------
extern "C" void kernel_launch(void* const* d_in, const int* in_sizes, int n_in,
                              void* d_out, int out_size)
{
    const float* Q_seq = (const float*)d_in[0];
    const float* K_seq = (const float*)d_in[1];
    const float* V_seq = (const float*)d_in[2];
    const int*   q_len = (const int*)d_in[3];
    const int*   v_len = (const int*)d_in[4];
    const float* WQ    = (const float*)d_in[5];
    const float* WK    = (const float*)d_in[6];
    const float* WV    = (const float*)d_in[7];
    float* Out = (float*)d_out;

    dim3 tgrid(DM / 32, DM / 32, 3);
    wt_kernel<<<tgrid, dim3(32, 8)>>>(WQ, WK, WV);

    dim3 pgrid(DM / 128, (BATCH * LEN) / 128, 3);
    proj_mma_kernel<<<pgrid, 256>>>(Q_seq, K_seq, V_seq, q_len, v_len);

    const int smem = 6 * TILEW * 4;   // 104448 bytes
    static bool attr_set = false;
    if (!attr_set) {
        cudaFuncSetAttribute(attn_mma_kernel,
                             cudaFuncAttributeMaxDynamicSharedMemorySize, smem);
        attr_set = true;
    }
    dim3 agrid(LEN / 64, NHEAD, BATCH);
    attn_mma_kernel<<<agrid, 128, smem>>>(q_len, v_len, Out);
}

// round 15
// speedup vs baseline: 5.6565x; 1.0661x over previous
#include <cuda_runtime.h>
#include <math.h>
#include <stdint.h>

#define NHEAD 16
#define DH    64
#define DM    1024
#define BATCH 2
#define LEN   2048

// Scratch (values stored as tf32-rounded f32 bits, ready for mma.sync):
// q,k in [B,H,L,DH] (q pre-scaled by 1/8); v TRANSPOSED in [B,H,DH,L]; W^T.
__device__ float g_q[(size_t)BATCH * NHEAD * LEN * DH];
__device__ float g_k[(size_t)BATCH * NHEAD * LEN * DH];
__device__ float g_v[(size_t)BATCH * NHEAD * LEN * DH];   // [B][H][DH][LEN]
__device__ float g_wt[(size_t)3 * DM * DM];               // tf32(W^T): [n][k]

__device__ __forceinline__ uint32_t f32_to_tf32(float x) {
    uint32_t r;
    asm("cvt.rna.tf32.f32 %0, %1;" : "=r"(r) : "f"(x));
    return r;
}

// m16n8k8 tf32 MMA (sm_80 baseline instruction, tensor core)
__device__ __forceinline__ void mma_tf32(float* c, const uint32_t* a,
                                         uint32_t b0, uint32_t b1) {
    asm volatile(
        "mma.sync.aligned.m16n8k8.row.col.f32.tf32.tf32.f32 "
        "{%0,%1,%2,%3}, {%4,%5,%6,%7}, {%8,%9}, {%0,%1,%2,%3};"
        : "+f"(c[0]), "+f"(c[1]), "+f"(c[2]), "+f"(c[3])
        : "r"(a[0]), "r"(a[1]), "r"(a[2]), "r"(a[3]), "r"(b0), "r"(b1));
}

#define CP_ASYNC16(dst_smem, src_gmem) \
    asm volatile("cp.async.cg.shared.global [%0], [%1], 16;" \
                 :: "r"(dst_smem), "l"(src_gmem))
#define CP_COMMIT() asm volatile("cp.async.commit_group;" ::: "memory")
#define CP_WAIT1()  asm volatile("cp.async.wait_group 1;" ::: "memory")
#define CP_WAIT0()  asm volatile("cp.async.wait_group 0;" ::: "memory")

// ---------------------------------------------------------------------------
// Weight transpose + tf32 pre-round: W[k][n] -> tf32(W^T)[n][k].
// ---------------------------------------------------------------------------
__global__ __launch_bounds__(256) void wt_kernel(
    const float* __restrict__ WQ, const float* __restrict__ WK,
    const float* __restrict__ WV)
{
    __shared__ float t[32][33];
    const float* W = (blockIdx.z == 0) ? WQ : (blockIdx.z == 1) ? WK : WV;
    float* WT = g_wt + (size_t)blockIdx.z * DM * DM;

    const int n0 = blockIdx.x * 32;
    const int k0 = blockIdx.y * 32;
    const int tx = threadIdx.x, ty = threadIdx.y;

    #pragma unroll
    for (int j = 0; j < 4; ++j)
        t[ty + j * 8][tx] = W[(size_t)(k0 + ty + j * 8) * DM + n0 + tx];
    __syncthreads();
    #pragma unroll
    for (int j = 0; j < 4; ++j)
        WT[(size_t)(n0 + ty + j * 8) * DM + k0 + tx] =
            __uint_as_float(f32_to_tf32(t[tx][ty + j * 8]));
}

// ---------------------------------------------------------------------------
// Projection GEMM on mma.sync tf32 with cp.async double-buffered K-chunks.
// A staged raw f32 (cvt at fragment consume); B pre-rounded tf32 (raw copy).
// Q (x1/8) / K -> [B,H,L,DH]; V -> [B,H,DH,L]. Dead tiles skipped.
// ---------------------------------------------------------------------------
#define BK 32
#define KPAD 36
#define NCHUNK (DM / BK)   // 32

__global__ __launch_bounds__(256, 2) void proj_mma_kernel(
    const float* __restrict__ Q, const float* __restrict__ K,
    const float* __restrict__ V,
    const int* __restrict__ qlen_p, const int* __restrict__ vlen_p)
{
    __shared__ uint32_t As[2][128][KPAD];   // raw f32 bits
    __shared__ uint32_t Bs[2][128][KPAD];   // tf32 bits

    const int z = blockIdx.z;
    const int m0 = blockIdx.y * 128;
    const int n0 = blockIdx.x * 128;

    {   // dead-tile skip (tiles never straddle batches)
        const int bb = m0 >> 11;
        const int l0 = m0 & (LEN - 1);
        const int len = (z == 0) ? qlen_p[bb] : vlen_p[bb];
        if (l0 >= len) return;
    }

    const float* X  = (z == 0) ? Q : (z == 1) ? K : V;
    const float* WT = g_wt + (size_t)z * DM * DM;
    float* O        = (z == 0) ? g_q : (z == 1) ? g_k : g_v;

    const int tid  = threadIdx.x;
    const int wid  = tid >> 5;
    const int lane = tid & 31;
    const int wm   = wid & 3;
    const int wn   = wid >> 2;
    const int g = lane >> 2;
    const int t = lane & 3;

    const uint32_t sma = (uint32_t)__cvta_generic_to_shared(As);
    const uint32_t smb = (uint32_t)__cvta_generic_to_shared(Bs);
    const uint32_t bufw = 128 * KPAD * 4;   // bytes per buffer

    // copy coords: 1024 float4 per tile / 256 threads = 4 each
    const int crow = tid >> 1;             // base pattern via idx
    (void)crow;

    const float* Xb = X + (size_t)m0 * DM;
    const float* Wb = WT + (size_t)n0 * DM;

    #define PROJ_STAGE(chunk, buf) do {                                        \
        const float* xp = Xb + (chunk) * BK;                                   \
        const float* wp = Wb + (chunk) * BK;                                   \
        _Pragma("unroll")                                                      \
        for (int p = 0; p < 4; ++p) {                                          \
            int idx = tid + p * 256;                                           \
            int row = idx >> 3, c4 = (idx & 7) * 4;                            \
            CP_ASYNC16(sma + (buf) * bufw + (row * KPAD + c4) * 4,             \
                       xp + (size_t)row * DM + c4);                            \
            CP_ASYNC16(smb + (buf) * bufw + (row * KPAD + c4) * 4,             \
                       wp + (size_t)row * DM + c4);                            \
        }                                                                      \
        CP_COMMIT();                                                           \
    } while (0)

    float acc[2][8][4];
    #pragma unroll
    for (int i = 0; i < 2; ++i)
        #pragma unroll
        for (int j = 0; j < 8; ++j)
            #pragma unroll
            for (int c = 0; c < 4; ++c) acc[i][j][c] = 0.f;

    PROJ_STAGE(0, 0);
    PROJ_STAGE(1, 1);

    for (int ch = 0; ch < NCHUNK; ++ch) {
        if (ch + 1 < NCHUNK) { CP_WAIT1(); } else { CP_WAIT0(); }
        __syncthreads();
        const int buf = ch & 1;

        #pragma unroll
        for (int ks = 0; ks < 4; ++ks) {
            const int kk = ks * 8;
            uint32_t a[2][4];
            #pragma unroll
            for (int i = 0; i < 2; ++i) {
                const int ar = wm * 32 + i * 16 + g;
                // A staged raw f32: convert at consume (same values as before)
                a[i][0] = f32_to_tf32(__uint_as_float(As[buf][ar][kk + t]));
                a[i][1] = f32_to_tf32(__uint_as_float(As[buf][ar + 8][kk + t]));
                a[i][2] = f32_to_tf32(__uint_as_float(As[buf][ar][kk + t + 4]));
                a[i][3] = f32_to_tf32(__uint_as_float(As[buf][ar + 8][kk + t + 4]));
            }
            #pragma unroll
            for (int j = 0; j < 8; ++j) {
                const int br = wn * 64 + j * 8 + g;
                uint32_t b0 = Bs[buf][br][kk + t];
                uint32_t b1 = Bs[buf][br][kk + t + 4];
                mma_tf32(acc[0][j], a[0], b0, b1);
                mma_tf32(acc[1][j], a[1], b0, b1);
            }
        }
        __syncthreads();

        if (ch + 2 < NCHUNK) PROJ_STAGE(ch + 2, buf);
    }
    #undef PROJ_STAGE

    const float scale = (z == 0) ? 0.125f : 1.0f;   // fold 1/sqrt(DH) into Q
    #pragma unroll
    for (int i = 0; i < 2; ++i) {
        #pragma unroll
        for (int j = 0; j < 8; ++j) {
            const int col  = n0 + wn * 64 + j * 8 + t * 2;
            const int head = col >> 6;
            const int cin  = col & 63;
            #pragma unroll
            for (int rr = 0; rr < 2; ++rr) {
                const int row = m0 + wm * 32 + i * 16 + g + rr * 8;
                const int bb = row >> 11, l = row & (LEN - 1);
                const float v0 = __uint_as_float(f32_to_tf32(acc[i][j][rr * 2] * scale));
                const float v1 = __uint_as_float(f32_to_tf32(acc[i][j][rr * 2 + 1] * scale));
                if (z != 2) {
                    float* dst = &O[(((size_t)bb * NHEAD + head) * LEN + l) * DH + cin];
                    *(float2*)dst = make_float2(v0, v1);
                } else {
                    float* base = &O[(((size_t)bb * NHEAD + head) * DH + cin) * LEN + l];
                    base[0]   = v0;
                    base[LEN] = v1;
                }
            }
        }
    }
}

// ---------------------------------------------------------------------------
// Flash attention on mma.sync tf32 with cp.async double-buffered K/V^T.
// Block = (b, h, 64 q-rows), 128 threads (4 warps, m16 slab per warp).
// Q fragments hoisted out of the K-tile loop (loop-invariant).
// smem: Qs[64][68], Kb[2][64][68], Vb[2][64][68], Ps[64][68] = 104.4 KB.
// ---------------------------------------------------------------------------
#define SPAD 68
#define TILEW (64 * SPAD)
#define NEGB 1e30f

__global__ __launch_bounds__(128, 2) void attn_mma_kernel(
    const int* __restrict__ qlen_p, const int* __restrict__ vlen_p,
    float* __restrict__ Out)
{
    extern __shared__ uint32_t dsm[];
    uint32_t* Qs = dsm;                 // [64][68]
    uint32_t* Kb0 = dsm + TILEW;        // double-buffered K
    uint32_t* Kb1 = dsm + 2 * TILEW;
    uint32_t* Vb0 = dsm + 3 * TILEW;    // double-buffered V^T
    uint32_t* Vb1 = dsm + 4 * TILEW;
    uint32_t* Ps  = dsm + 5 * TILEW;    // [64][68]

    const int b = blockIdx.z;
    const int h = blockIdx.y;
    const int qbase = blockIdx.x * 64;
    const int tid = threadIdx.x;
    const int w = tid >> 5;
    const int lane = tid & 31;
    const int g = lane >> 2;
    const int t = lane & 3;
    const int qlen = qlen_p[b];
    const int vlen = vlen_p[b];

    float* outc = Out + ((size_t)b * LEN) * DM + h * DH;

    if (qbase >= qlen) {   // dead block: zero 64x64 and exit
        float4 zero = make_float4(0.f, 0.f, 0.f, 0.f);
        for (int i = tid; i < 64 * 16; i += 128) {
            int r = i >> 4, c4 = (i & 15) * 4;
            *(float4*)&outc[(size_t)(qbase + r) * DM + c4] = zero;
        }
        return;
    }

    const float* qg   = g_q + (((size_t)b * NHEAD + h) * LEN + qbase) * DH;
    const float* kg0  = g_k + (((size_t)b * NHEAD + h) * LEN) * DH;
    const float* vtg0 = g_v + (((size_t)b * NHEAD + h) * DH) * LEN;

    const uint32_t smem_base = (uint32_t)__cvta_generic_to_shared(dsm);
    const int ntile = (vlen + 63) >> 6;

    // per-thread copy coords: 1024 float4 per 64x64 tile / 128 threads = 8
    const int crow = tid >> 4;          // base row 0..7 (stride 8)
    const int cc4  = (tid & 15) * 4;    // word col 0..60

    // ---- prologue: Q + tile0 (group A), tile1 (group B) ----
    {
        #pragma unroll
        for (int i = 0; i < 8; ++i) {
            int r = crow + i * 8;
            CP_ASYNC16(smem_base + (r * SPAD + cc4) * 4, qg + (size_t)r * DH + cc4);
        }
        const float* kg  = kg0;
        const float* vtg = vtg0;
        #pragma unroll
        for (int i = 0; i < 8; ++i) {
            int r = crow + i * 8;
            CP_ASYNC16(smem_base + (TILEW + r * SPAD + cc4) * 4, kg + (size_t)r * DH + cc4);
            CP_ASYNC16(smem_base + (3 * TILEW + r * SPAD + cc4) * 4, vtg + (size_t)r * LEN + cc4);
        }
        CP_COMMIT();
        if (ntile > 1) {
            kg  = kg0 + (size_t)64 * DH;
            vtg = vtg0 + 64;
            #pragma unroll
            for (int i = 0; i < 8; ++i) {
                int r = crow + i * 8;
                CP_ASYNC16(smem_base + (2 * TILEW + r * SPAD + cc4) * 4, kg + (size_t)r * DH + cc4);
                CP_ASYNC16(smem_base + (4 * TILEW + r * SPAD + cc4) * 4, vtg + (size_t)r * LEN + cc4);
            }
            CP_COMMIT();
        }
    }

    const int mrow = w * 16 + g;

    float oacc[8][4];
    #pragma unroll
    for (int j = 0; j < 8; ++j)
        #pragma unroll
        for (int c = 0; c < 4; ++c) oacc[j][c] = 0.f;
    float m0 = -NEGB, m1 = -NEGB, l0 = 0.f, l1 = 0.f;

    // ---- first-tile wait, then hoist loop-invariant Q fragments ----
    if (ntile > 1) { CP_WAIT1(); } else { CP_WAIT0(); }
    __syncthreads();

    uint32_t qa[8][4];
    #pragma unroll
    for (int s = 0; s < 8; ++s) {
        qa[s][0] = Qs[mrow * SPAD + s * 8 + t];
        qa[s][1] = Qs[(mrow + 8) * SPAD + s * 8 + t];
        qa[s][2] = Qs[mrow * SPAD + s * 8 + t + 4];
        qa[s][3] = Qs[(mrow + 8) * SPAD + s * 8 + t + 4];
    }

    for (int kt = 0; kt < ntile; ++kt) {
        if (kt > 0) {
            if (kt + 1 < ntile) { CP_WAIT1(); } else { CP_WAIT0(); }
            __syncthreads();
        }

        uint32_t* Ks  = (kt & 1) ? Kb1 : Kb0;
        uint32_t* VTs = (kt & 1) ? Vb1 : Vb0;
        const int k0 = kt * 64;

        // ---- S = Q K^T ----
        float sa[8][4];
        #pragma unroll
        for (int j = 0; j < 8; ++j)
            #pragma unroll
            for (int c = 0; c < 4; ++c) sa[j][c] = 0.f;
        #pragma unroll
        for (int s = 0; s < 8; ++s)
            #pragma unroll
            for (int j = 0; j < 8; ++j) {
                uint32_t b0 = Ks[(j * 8 + g) * SPAD + s * 8 + t];
                uint32_t b1 = Ks[(j * 8 + g) * SPAD + s * 8 + t + 4];
                mma_tf32(sa[j], qa[s], b0, b1);
            }

        // ---- mask + row max ----
        float tx0 = -NEGB, tx1 = -NEGB;
        #pragma unroll
        for (int j = 0; j < 8; ++j) {
            int key = k0 + j * 8 + 2 * t;
            if (key >= vlen)     { sa[j][0] = -NEGB; sa[j][2] = -NEGB; }
            if (key + 1 >= vlen) { sa[j][1] = -NEGB; sa[j][3] = -NEGB; }
            tx0 = fmaxf(tx0, fmaxf(sa[j][0], sa[j][1]));
            tx1 = fmaxf(tx1, fmaxf(sa[j][2], sa[j][3]));
        }
        tx0 = fmaxf(tx0, __shfl_xor_sync(0xffffffffu, tx0, 1));
        tx0 = fmaxf(tx0, __shfl_xor_sync(0xffffffffu, tx0, 2));
        tx1 = fmaxf(tx1, __shfl_xor_sync(0xffffffffu, tx1, 1));
        tx1 = fmaxf(tx1, __shfl_xor_sync(0xffffffffu, tx1, 2));

        float mn0 = fmaxf(m0, tx0), mn1 = fmaxf(m1, tx1);
        float cr0 = __expf(m0 - mn0), cr1 = __expf(m1 - mn1);
        l0 *= cr0; l1 *= cr1;
        #pragma unroll
        for (int j = 0; j < 8; ++j) {
            oacc[j][0] *= cr0; oacc[j][1] *= cr0;
            oacc[j][2] *= cr1; oacc[j][3] *= cr1;
        }

        // ---- exp, l accumulation, P -> smem (tf32) ----
        #pragma unroll
        for (int j = 0; j < 8; ++j) {
            float p0 = __expf(sa[j][0] - mn0);
            float p1 = __expf(sa[j][1] - mn0);
            float p2 = __expf(sa[j][2] - mn1);
            float p3 = __expf(sa[j][3] - mn1);
            l0 += p0 + p1;  l1 += p2 + p3;
            Ps[mrow * SPAD + j * 8 + 2 * t]           = f32_to_tf32(p0);
            Ps[mrow * SPAD + j * 8 + 2 * t + 1]       = f32_to_tf32(p1);
            Ps[(mrow + 8) * SPAD + j * 8 + 2 * t]     = f32_to_tf32(p2);
            Ps[(mrow + 8) * SPAD + j * 8 + 2 * t + 1] = f32_to_tf32(p3);
        }
        m0 = mn0; m1 = mn1;
        __syncwarp();

        // ---- O += P V ----
        #pragma unroll
        for (int s = 0; s < 8; ++s) {
            uint32_t pa[4];
            pa[0] = Ps[mrow * SPAD + s * 8 + t];
            pa[1] = Ps[(mrow + 8) * SPAD + s * 8 + t];
            pa[2] = Ps[mrow * SPAD + s * 8 + t + 4];
            pa[3] = Ps[(mrow + 8) * SPAD + s * 8 + t + 4];
            #pragma unroll
            for (int j = 0; j < 8; ++j) {
                uint32_t b0 = VTs[(j * 8 + g) * SPAD + s * 8 + t];
                uint32_t b1 = VTs[(j * 8 + g) * SPAD + s * 8 + t + 4];
                mma_tf32(oacc[j], pa, b0, b1);
            }
        }
        __syncthreads();

        // ---- prefetch tile kt+2 into the buffer just freed ----
        if (kt + 2 < ntile) {
            const int kn = (kt + 2) * 64;
            const float* kg  = kg0 + (size_t)kn * DH;
            const float* vtg = vtg0 + kn;
            const uint32_t koff = ((kt & 1) ? 2u : 1u) * TILEW;
            const uint32_t voff = ((kt & 1) ? 4u : 3u) * TILEW;
            #pragma unroll
            for (int i = 0; i < 8; ++i) {
                int r = crow + i * 8;
                CP_ASYNC16(smem_base + (koff + r * SPAD + cc4) * 4, kg + (size_t)r * DH + cc4);
                CP_ASYNC16(smem_base + (voff + r * SPAD + cc4) * 4, vtg + (size_t)r * LEN + cc4);
            }
            CP_COMMIT();
        }
    }

    // ---- epilogue: reduce l across quad, normalize, masked store ----
    l0 += __shfl_xor_sync(0xffffffffu, l0, 1);
    l0 += __shfl_xor_sync(0xffffffffu, l0, 2);
    l1 += __shfl_xor_sync(0xffffffffu, l1, 1);
    l1 += __shfl_xor_sync(0xffffffffu, l1, 2);
    const float inv0 = 1.0f / l0, inv1 = 1.0f / l1;

    const int r0 = qbase + mrow;
    const int r1 = r0 + 8;
    const bool a0 = (r0 < qlen), a1 = (r1 < qlen);
    #pragma unroll
    for (int j = 0; j < 8; ++j) {
        const int col = j * 8 + 2 * t;
        float2 v0 = a0 ? make_float2(oacc[j][0] * inv0, oacc[j][1] * inv0)
                       : make_float2(0.f, 0.f);
        *(float2*)&outc[(size_t)r0 * DM + col] = v0;
        float2 v1 = a1 ? make_float2(oacc[j][2] * inv1, oacc[j][3] * inv1)
                       : make_float2(0.f, 0.f);
        *(float2*)&outc[(size_t)r1 * DM + col] = v1;
    }
}

// ---------------------------------------------------------------------------
extern "C" void kernel_launch(void* const* d_in, const int* in_sizes, int n_in,
                              void* d_out, int out_size)
{
    const float* Q_seq = (const float*)d_in[0];
    const float* K_seq = (const float*)d_in[1];
    const float* V_seq = (const float*)d_in[2];
    const int*   q_len = (const int*)d_in[3];
    const int*   v_len = (const int*)d_in[4];
    const float* WQ    = (const float*)d_in[5];
    const float* WK    = (const float*)d_in[6];
    const float* WV    = (const float*)d_in[7];
    float* Out = (float*)d_out;

    dim3 tgrid(DM / 32, DM / 32, 3);
    wt_kernel<<<tgrid, dim3(32, 8)>>>(WQ, WK, WV);

    dim3 pgrid(DM / 128, (BATCH * LEN) / 128, 3);
    proj_mma_kernel<<<pgrid, 256>>>(Q_seq, K_seq, V_seq, q_len, v_len);

    const int smem = 6 * TILEW * 4;   // 104448 bytes
    static bool attr_set = false;
    if (!attr_set) {
        cudaFuncSetAttribute(attn_mma_kernel,
                             cudaFuncAttributeMaxDynamicSharedMemorySize, smem);
        attr_set = true;
    }
    dim3 agrid(LEN / 64, NHEAD, BATCH);
    attn_mma_kernel<<<agrid, 128, smem>>>(q_len, v_len, Out);
}